// round 7
// baseline (speedup 1.0000x reference)
#include <cuda_runtime.h>

#define BQ   4
#define NPT  16384
#define MQ   2048
#define CF   128
#define NS   32
#define PTOT (BQ*MQ)        // 8192 query points
#define COLS (PTOT*NS)      // 262144 GEMM columns
#define R2   9.0f
#define EPSV 1e-5f

// ---------------- static scratch (allocation-free rule) ----------------
__device__ float d_h0[64*PTOT];
__device__ float d_h1[3*PTOT];
__device__ float d_nxyz[PTOT*3];
__device__ float d_featT[BQ*NPT*CF];      // 32 MB: features transposed to [b][n][c]
__device__ int   d_idx[COLS];
__device__ float d_out0[128*COLS];        // 134 MB: pre-BN layer-0 activations
__device__ float d_pmax[256*PTOT];
__device__ float d_pmin[256*PTOT];
__device__ float d_stats[768];            // [0:128) m0sum [128:256) m0sq [256:512) m1sum [512:768) m1sq
__device__ float d_sc0[64], d_bi0[64], d_sc1[3], d_bi1[3];
__device__ float d_scm0[128], d_bim0[128], d_scm1[256], d_bim1[256];

// ---------------- packed f32x2 helpers ----------------
__device__ __forceinline__ unsigned long long pack2(float x){
    unsigned long long r; unsigned u = __float_as_uint(x);
    asm("mov.b64 %0, {%1, %1};" : "=l"(r) : "r"(u));
    return r;
}
__device__ __forceinline__ unsigned long long ffma2(unsigned long long a,
                                                    unsigned long long b,
                                                    unsigned long long c){
    unsigned long long d;
    asm("fma.rn.f32x2 %0, %1, %2, %3;" : "=l"(d) : "l"(a), "l"(b), "l"(c));
    return d;
}
__device__ __forceinline__ void unpack2(unsigned long long v, float& lo, float& hi){
    unsigned a, b;
    asm("mov.b64 {%0, %1}, %2;" : "=r"(a), "=r"(b) : "l"(v));
    lo = __uint_as_float(a); hi = __uint_as_float(b);
}

// ---------------- misc small kernels ----------------
__global__ void kzero(){
    int i = blockIdx.x*blockDim.x + threadIdx.x;
    if (i < 768) d_stats[i] = 0.f;
}

// shift layer 0 pre-BN: h0[c][p] = sum_d w0[c][d]*ffps[p][d]
__global__ void ks1(const float* __restrict__ ffps, const float* __restrict__ w0){
    int p = blockIdx.x*blockDim.x + threadIdx.x;
    float f0 = ffps[p*3+0], f1 = ffps[p*3+1], f2 = ffps[p*3+2];
    #pragma unroll 4
    for (int c = 0; c < 64; c++){
        float v = w0[c*3+0]*f0 + w0[c*3+1]*f1 + w0[c*3+2]*f2;
        d_h0[c*PTOT + p] = v;
    }
}

// generic per-channel stats over PTOT elements (shift layers)
__global__ void kstat(int which, const float* __restrict__ g, const float* __restrict__ bb){
    __shared__ float ss[256], sq[256];
    int c = blockIdx.x;
    const float* buf = (which == 0 ? d_h0 : d_h1) + c*PTOT;
    float s = 0.f, q = 0.f;
    for (int i = threadIdx.x; i < PTOT; i += 256){
        float v = buf[i]; s += v; q = fmaf(v, v, q);
    }
    ss[threadIdx.x] = s; sq[threadIdx.x] = q; __syncthreads();
    for (int o = 128; o > 0; o >>= 1){
        if (threadIdx.x < o){
            ss[threadIdx.x] += ss[threadIdx.x+o];
            sq[threadIdx.x] += sq[threadIdx.x+o];
        }
        __syncthreads();
    }
    if (threadIdx.x == 0){
        float mean = ss[0] / (float)PTOT;
        float var  = sq[0] / (float)PTOT - mean*mean;
        float scl  = g[c] * rsqrtf(var + EPSV);
        if (which == 0){ d_sc0[c] = scl; d_bi0[c] = fmaf(-mean, scl, bb[c]); }
        else           { d_sc1[c] = scl; d_bi1[c] = fmaf(-mean, scl, bb[c]); }
    }
}

// shift layer 1 pre-BN: h1[o][p] = sum_c w1[o][c]*relu(bn(h0[c][p]))
__global__ void ks2(const float* __restrict__ w1){
    int p = blockIdx.x*blockDim.x + threadIdx.x;
    float a0 = 0.f, a1 = 0.f, a2 = 0.f;
    #pragma unroll 4
    for (int c = 0; c < 64; c++){
        float v = fmaxf(fmaf(d_sc0[c], d_h0[c*PTOT + p], d_bi0[c]), 0.f);
        a0 = fmaf(w1[c],       v, a0);
        a1 = fmaf(w1[64 + c],  v, a1);
        a2 = fmaf(w1[128 + c], v, a2);
    }
    d_h1[p] = a0; d_h1[PTOT + p] = a1; d_h1[2*PTOT + p] = a2;
}

// apply bn+relu -> new_xyz[p][3]
__global__ void ks3(){
    int p = blockIdx.x*blockDim.x + threadIdx.x;
    #pragma unroll
    for (int o = 0; o < 3; o++)
        d_nxyz[p*3 + o] = fmaxf(fmaf(d_sc1[o], d_h1[o*PTOT + p], d_bi1[o]), 0.f);
}

// transpose features: (B,C,N) -> (B,N,C)
__global__ void ktr(const float* __restrict__ feat){
    __shared__ float t[32][33];
    int b = blockIdx.z, n0 = blockIdx.x*32, c0 = blockIdx.y*32;
    for (int i = threadIdx.y; i < 32; i += 8)
        t[i][threadIdx.x] = feat[((size_t)b*CF + (c0+i))*NPT + n0 + threadIdx.x];
    __syncthreads();
    for (int i = threadIdx.y; i < 32; i += 8)
        d_featT[((size_t)b*NPT + (n0+i))*CF + c0 + threadIdx.x] = t[threadIdx.x][i];
}

// ball query: warp per query, first NS indices with d2 < R2, padded with first hit
__global__ void kballq(const float* __restrict__ bxyz){
    int gw = (blockIdx.x*blockDim.x + threadIdx.x) >> 5;
    int lane = threadIdx.x & 31;
    int b = gw >> 11;                 // / MQ
    float q0 = d_nxyz[gw*3+0], q1 = d_nxyz[gw*3+1], q2 = d_nxyz[gw*3+2];
    float qq = q0*q0 + q1*q1 + q2*q2;
    const float* xb = bxyz + (size_t)b*NPT*3;
    int cnt = 0, firstIdx = -1;
    for (int base = 0; base < NPT; base += 32){
        int n = base + lane;
        float x0 = xb[n*3+0], x1 = xb[n*3+1], x2 = xb[n*3+2];
        float xx = x0*x0 + x1*x1 + x2*x2;
        float dot = q0*x0 + q1*x1 + q2*x2;
        float d2 = (qq + xx) - 2.0f*dot;
        bool hit = d2 < R2;
        unsigned bal = __ballot_sync(0xffffffffu, hit);
        if (firstIdx < 0 && bal) firstIdx = base + __ffs(bal) - 1;
        if (hit){
            int pos = cnt + __popc(bal & ((1u << lane) - 1u));
            if (pos < NS) d_idx[gw*NS + pos] = n;
        }
        cnt += __popc(bal);
        if (cnt >= NS) break;
    }
    if (cnt < NS){
        int f = (firstIdx < 0) ? 0 : firstIdx;
        if (lane >= cnt) d_idx[gw*NS + lane] = f;
    }
}

// ---------------- GEMM 1: out0 = w0(128x131) @ [rel;feat], + channel stats ----------------
// smem: As [131][129] (k-major W), Bs [131][130] columns
#define G1_SMEM ((16900 + 131*130) * 4)
__global__ void __launch_bounds__(256, 1) kg1(const float* __restrict__ w0,
                                              const float* __restrict__ bxyz){
    extern __shared__ float sm[];
    float* As = sm;
    float* Bs = sm + 16900;
    const int tid = threadIdx.x;
    const int tx = tid & 15, ty = tid >> 4;
    const int jb = blockIdx.x * 128;

    for (int e = tid; e < 128*131; e += 256){
        int r = e / 131, k = e - r*131;
        As[k*129 + r] = w0[e];
    }
    {
        int col = tid >> 1, half = tid & 1;
        int j = jb + col;
        int b = j >> 16;
        int rem = j & 65535;
        int m = rem >> 5;
        int n = d_idx[j];
        const float* fp = d_featT + ((size_t)(b*NPT + n) * CF);
        int cb = half << 6;
        #pragma unroll
        for (int c4 = 0; c4 < 16; c4++){
            float4 v = *(const float4*)(fp + cb + c4*4);
            int kk = 3 + cb + c4*4;
            Bs[kk*130 + col]     = v.x;
            Bs[(kk+1)*130 + col] = v.y;
            Bs[(kk+2)*130 + col] = v.z;
            Bs[(kk+3)*130 + col] = v.w;
        }
        if (half == 0){
            const float* xp = bxyz + (size_t)(b*NPT + n)*3;
            const float* qp = d_nxyz + (size_t)(b*MQ + m)*3;
            Bs[col]       = xp[0] - qp[0];
            Bs[130 + col] = xp[1] - qp[1];
            Bs[260 + col] = xp[2] - qp[2];
        }
    }
    __syncthreads();

    unsigned long long acc[8][4];
    #pragma unroll
    for (int i = 0; i < 8; i++)
        #pragma unroll
        for (int j = 0; j < 4; j++) acc[i][j] = 0ull;

    for (int k = 0; k < 131; k++){
        unsigned long long av[8], bv[4];
        #pragma unroll
        for (int i = 0; i < 8; i++) av[i] = pack2(As[k*129 + ty + 16*i]);
        #pragma unroll
        for (int j = 0; j < 4; j++)
            bv[j] = *(const unsigned long long*)(Bs + k*130 + 2*tx + 32*j);
        #pragma unroll
        for (int i = 0; i < 8; i++)
            #pragma unroll
            for (int j = 0; j < 4; j++) acc[i][j] = ffma2(av[i], bv[j], acc[i][j]);
    }
    __syncthreads();

    float* red = sm;                 // 256 floats: [0:128) sum, [128:256) sq
    red[tid] = 0.f;
    __syncthreads();
    #pragma unroll
    for (int i = 0; i < 8; i++){
        int r = ty + 16*i;
        float rs = 0.f, rq = 0.f;
        #pragma unroll
        for (int j = 0; j < 4; j++){
            float lo, hi; unpack2(acc[i][j], lo, hi);
            int c = 2*tx + 32*j;
            *(float2*)(d_out0 + (size_t)r*COLS + jb + c) = make_float2(lo, hi);
            rs += lo + hi; rq += lo*lo + hi*hi;
        }
        atomicAdd(&red[r], rs);
        atomicAdd(&red[128 + r], rq);
    }
    __syncthreads();
    if (tid < 128){
        atomicAdd(&d_stats[tid],       red[tid]);
        atomicAdd(&d_stats[128 + tid], red[128 + tid]);
    }
}

// finalize BN scale/bias for mlp layers from accumulated stats
__global__ void kfm(int which, const float* __restrict__ g, const float* __restrict__ bb){
    int c = threadIdx.x;
    float inv = 1.0f / (float)COLS;
    int so = (which == 0) ? 0 : 256;
    int qo = (which == 0) ? 128 : 512;
    float mean = d_stats[so + c] * inv;
    float var  = d_stats[qo + c] * inv - mean*mean;
    float scl  = g[c] * rsqrtf(var + EPSV);
    if (which == 0){ d_scm0[c] = scl; d_bim0[c] = fmaf(-mean, scl, bb[c]); }
    else           { d_scm1[c] = scl; d_bim1[c] = fmaf(-mean, scl, bb[c]); }
}

// ---------------- GEMM 2: z1 = w1(256x128) @ relu(bn(out0)); fused stats + max/min pool ----------------
// grid (2048, 2): y = row half. smem: As [128][129], Bs [128][130]
#define G2_SMEM ((128*129 + 128*130) * 4)
__global__ void __launch_bounds__(256, 1) kg2(const float* __restrict__ w1){
    extern __shared__ float sm[];
    float* As = sm;
    float* Bs = sm + 128*129;
    const int tid = threadIdx.x;
    const int tx = tid & 15, ty = tid >> 4;
    const int jb = blockIdx.x * 128;
    const int rowOff = blockIdx.y * 128;

    for (int e = tid; e < 128*128; e += 256){
        int r = e >> 7, k = e & 127;
        As[k*129 + r] = w1[(rowOff + r)*128 + k];
    }
    for (int e = tid; e < 128*128; e += 256){
        int k = e >> 7, col = e & 127;
        float v = d_out0[(size_t)k*COLS + jb + col];
        Bs[k*130 + col] = fmaxf(fmaf(d_scm0[k], v, d_bim0[k]), 0.f);
    }
    __syncthreads();

    unsigned long long acc[8][4];
    #pragma unroll
    for (int i = 0; i < 8; i++)
        #pragma unroll
        for (int j = 0; j < 4; j++) acc[i][j] = 0ull;

    for (int k = 0; k < 128; k++){
        unsigned long long av[8], bv[4];
        #pragma unroll
        for (int i = 0; i < 8; i++) av[i] = pack2(As[k*129 + ty + 16*i]);
        #pragma unroll
        for (int j = 0; j < 4; j++)
            bv[j] = *(const unsigned long long*)(Bs + k*130 + 2*tx + 32*j);
        #pragma unroll
        for (int i = 0; i < 8; i++)
            #pragma unroll
            for (int j = 0; j < 4; j++) acc[i][j] = ffma2(av[i], bv[j], acc[i][j]);
    }
    __syncthreads();

    float* red = sm;                // 256 floats: [0:128) sum, [128:256) sq (local rows)
    red[tid] = 0.f;
    __syncthreads();
    #pragma unroll
    for (int i = 0; i < 8; i++){
        int rl = ty + 16*i;
        int rg = rowOff + rl;
        float rs = 0.f, rq = 0.f;
        #pragma unroll
        for (int j = 0; j < 4; j++){
            float lo, hi; unpack2(acc[i][j], lo, hi);
            rs += lo + hi; rq += lo*lo + hi*hi;
            float mx = fmaxf(lo, hi), mn = fminf(lo, hi);
            #pragma unroll
            for (int off = 8; off > 0; off >>= 1){
                mx = fmaxf(mx, __shfl_down_sync(0xffffffffu, mx, off, 16));
                mn = fminf(mn, __shfl_down_sync(0xffffffffu, mn, off, 16));
            }
            if (tx == 0){
                int q = (jb >> 5) + j;
                d_pmax[(size_t)rg*PTOT + q] = mx;
                d_pmin[(size_t)rg*PTOT + q] = mn;
            }
        }
        atomicAdd(&red[rl], rs);
        atomicAdd(&red[128 + rl], rq);
    }
    __syncthreads();
    if (tid < 128){
        atomicAdd(&d_stats[256 + rowOff + tid], red[tid]);
        atomicAdd(&d_stats[512 + rowOff + tid], red[128 + tid]);
    }
}

// final: out[p][c] = relu(s*pooled + t), pooled = max if s>=0 else min
__global__ void kfin(float* __restrict__ out){
    int c = threadIdx.x;
    int p = blockIdx.x;
    float s = d_scm1[c], t = d_bim1[c];
    float v = (s >= 0.f) ? d_pmax[(size_t)c*PTOT + p] : d_pmin[(size_t)c*PTOT + p];
    out[(size_t)p*256 + c] = fmaxf(fmaf(s, v, t), 0.f);
}

// ---------------- launch ----------------
extern "C" void kernel_launch(void* const* d_in, const int* in_sizes, int n_in,
                              void* d_out, int out_size){
    (void)in_sizes; (void)n_in; (void)out_size;
    const float* ffps = (const float*)d_in[0];
    const float* bxyz = (const float*)d_in[1];
    const float* bfeat= (const float*)d_in[2];
    const float* sw0  = (const float*)d_in[3];
    const float* sg0  = (const float*)d_in[4];
    const float* sb0  = (const float*)d_in[5];
    const float* sw1  = (const float*)d_in[6];
    const float* sg1  = (const float*)d_in[7];
    const float* sb1  = (const float*)d_in[8];
    const float* mw0  = (const float*)d_in[9];
    const float* mg0  = (const float*)d_in[10];
    const float* mb0  = (const float*)d_in[11];
    const float* mw1  = (const float*)d_in[12];
    const float* mg1  = (const float*)d_in[13];
    const float* mb1  = (const float*)d_in[14];
    float* out = (float*)d_out;

    cudaFuncSetAttribute(kg1, cudaFuncAttributeMaxDynamicSharedMemorySize, G1_SMEM);
    cudaFuncSetAttribute(kg2, cudaFuncAttributeMaxDynamicSharedMemorySize, G2_SMEM);

    kzero<<<3, 256>>>();
    ks1<<<PTOT/256, 256>>>(ffps, sw0);
    kstat<<<64, 256>>>(0, sg0, sb0);
    ks2<<<PTOT/256, 256>>>(sw1);
    kstat<<<3, 256>>>(1, sg1, sb1);
    ks3<<<PTOT/256, 256>>>();
    ktr<<<dim3(NPT/32, CF/32, BQ), dim3(32, 8)>>>(bfeat);
    kballq<<<PTOT/8, 256>>>(bxyz);
    kg1<<<COLS/128, 256, G1_SMEM>>>(mw0, bxyz);
    kfm<<<1, 128>>>(0, mg0, mb0);
    kg2<<<dim3(COLS/128, 2), 256, G2_SMEM>>>(mw1);
    kfm<<<1, 256>>>(1, mg1, mb1);
    kfin<<<PTOT, 256>>>(out);
}

// round 8
// speedup vs baseline: 2.7580x; 2.7580x over previous
#include <cuda_runtime.h>
#include <cuda_bf16.h>
#include <cstdint>

#define BQ   4
#define NPT  16384
#define MQ   2048
#define CF   128
#define NS   32
#define PTOT (BQ*MQ)        // 8192 query points
#define COLS (PTOT*NS)      // 262144 GEMM columns
#define R2   9.0f
#define EPSV 1e-5f

// ---------------- static scratch (allocation-free rule) ----------------
__device__ float d_h0[64*PTOT];
__device__ float d_h1[3*PTOT];
__device__ float d_nxyz[PTOT*3];
__device__ __nv_bfloat16 d_fh[(size_t)BQ*NPT*CF];   // features hi  [b][n][c]
__device__ __nv_bfloat16 d_fl[(size_t)BQ*NPT*CF];   // features lo
__device__ int   d_idx[COLS];
__device__ float d_out0[(size_t)COLS*128];          // pre-BN layer-0 acts, [j][k]
__device__ float d_pmax[(size_t)PTOT*256];          // [q][c]
__device__ float d_pmin[(size_t)PTOT*256];
__device__ float d_stats[768];
__device__ float d_sc0[64], d_bi0[64], d_sc1[3], d_bi1[3];
__device__ float d_scm0[128], d_bim0[128], d_scm1[256], d_bim1[256];

// ---------------- helpers ----------------
__device__ __forceinline__ void bsplit(float x, __nv_bfloat16& h, __nv_bfloat16& l){
    h = __float2bfloat16(x);
    l = __float2bfloat16(x - __bfloat162float(h));
}
__device__ __forceinline__ void mma_bf16(float& c0, float& c1, float& c2, float& c3,
                                         unsigned a0, unsigned a1, unsigned a2, unsigned a3,
                                         unsigned b0, unsigned b1){
    asm volatile("mma.sync.aligned.m16n8k16.row.col.f32.bf16.bf16.f32 "
        "{%0,%1,%2,%3}, {%4,%5,%6,%7}, {%8,%9}, {%0,%1,%2,%3};"
        : "+f"(c0), "+f"(c1), "+f"(c2), "+f"(c3)
        : "r"(a0), "r"(a1), "r"(a2), "r"(a3), "r"(b0), "r"(b1));
}
__device__ __forceinline__ float red4sum(float v){
    v += __shfl_xor_sync(0xffffffffu, v, 1, 4);
    v += __shfl_xor_sync(0xffffffffu, v, 2, 4);
    return v;
}
__device__ __forceinline__ float red4max(float v){
    v = fmaxf(v, __shfl_xor_sync(0xffffffffu, v, 1, 4));
    v = fmaxf(v, __shfl_xor_sync(0xffffffffu, v, 2, 4));
    return v;
}
__device__ __forceinline__ float red4min(float v){
    v = fminf(v, __shfl_xor_sync(0xffffffffu, v, 1, 4));
    v = fminf(v, __shfl_xor_sync(0xffffffffu, v, 2, 4));
    return v;
}

// ---------------- small kernels (unchanged logic) ----------------
__global__ void kzero(){
    int i = blockIdx.x*blockDim.x + threadIdx.x;
    if (i < 768) d_stats[i] = 0.f;
}

__global__ void ks1(const float* __restrict__ ffps, const float* __restrict__ w0){
    int p = blockIdx.x*blockDim.x + threadIdx.x;
    float f0 = ffps[p*3+0], f1 = ffps[p*3+1], f2 = ffps[p*3+2];
    #pragma unroll 4
    for (int c = 0; c < 64; c++){
        float v = w0[c*3+0]*f0 + w0[c*3+1]*f1 + w0[c*3+2]*f2;
        d_h0[c*PTOT + p] = v;
    }
}

__global__ void kstat(int which, const float* __restrict__ g, const float* __restrict__ bb){
    __shared__ float ss[256], sq[256];
    int c = blockIdx.x;
    const float* buf = (which == 0 ? d_h0 : d_h1) + c*PTOT;
    float s = 0.f, q = 0.f;
    for (int i = threadIdx.x; i < PTOT; i += 256){
        float v = buf[i]; s += v; q = fmaf(v, v, q);
    }
    ss[threadIdx.x] = s; sq[threadIdx.x] = q; __syncthreads();
    for (int o = 128; o > 0; o >>= 1){
        if (threadIdx.x < o){
            ss[threadIdx.x] += ss[threadIdx.x+o];
            sq[threadIdx.x] += sq[threadIdx.x+o];
        }
        __syncthreads();
    }
    if (threadIdx.x == 0){
        float mean = ss[0] / (float)PTOT;
        float var  = sq[0] / (float)PTOT - mean*mean;
        float scl  = g[c] * rsqrtf(var + EPSV);
        if (which == 0){ d_sc0[c] = scl; d_bi0[c] = fmaf(-mean, scl, bb[c]); }
        else           { d_sc1[c] = scl; d_bi1[c] = fmaf(-mean, scl, bb[c]); }
    }
}

__global__ void ks2(const float* __restrict__ w1){
    int p = blockIdx.x*blockDim.x + threadIdx.x;
    float a0 = 0.f, a1 = 0.f, a2 = 0.f;
    #pragma unroll 4
    for (int c = 0; c < 64; c++){
        float v = fmaxf(fmaf(d_sc0[c], d_h0[c*PTOT + p], d_bi0[c]), 0.f);
        a0 = fmaf(w1[c],       v, a0);
        a1 = fmaf(w1[64 + c],  v, a1);
        a2 = fmaf(w1[128 + c], v, a2);
    }
    d_h1[p] = a0; d_h1[PTOT + p] = a1; d_h1[2*PTOT + p] = a2;
}

__global__ void ks3(){
    int p = blockIdx.x*blockDim.x + threadIdx.x;
    #pragma unroll
    for (int o = 0; o < 3; o++)
        d_nxyz[p*3 + o] = fmaxf(fmaf(d_sc1[o], d_h1[o*PTOT + p], d_bi1[o]), 0.f);
}

// transpose features (B,C,N) -> [b][n][c], split to bf16 hi/lo
__global__ void ktr(const float* __restrict__ feat){
    __shared__ float t[32][33];
    int b = blockIdx.z, n0 = blockIdx.x*32, c0 = blockIdx.y*32;
    for (int i = threadIdx.y; i < 32; i += 8)
        t[i][threadIdx.x] = feat[((size_t)b*CF + (c0+i))*NPT + n0 + threadIdx.x];
    __syncthreads();
    for (int i = threadIdx.y; i < 32; i += 8){
        float v = t[threadIdx.x][i];
        __nv_bfloat16 h, l; bsplit(v, h, l);
        size_t o = ((size_t)b*NPT + (n0+i))*CF + c0 + threadIdx.x;
        d_fh[o] = h; d_fl[o] = l;
    }
}

__global__ void kballq(const float* __restrict__ bxyz){
    int gw = (blockIdx.x*blockDim.x + threadIdx.x) >> 5;
    int lane = threadIdx.x & 31;
    int b = gw >> 11;
    float q0 = d_nxyz[gw*3+0], q1 = d_nxyz[gw*3+1], q2 = d_nxyz[gw*3+2];
    float qq = q0*q0 + q1*q1 + q2*q2;
    const float* xb = bxyz + (size_t)b*NPT*3;
    int cnt = 0, firstIdx = -1;
    for (int base = 0; base < NPT; base += 32){
        int n = base + lane;
        float x0 = xb[n*3+0], x1 = xb[n*3+1], x2 = xb[n*3+2];
        float xx = x0*x0 + x1*x1 + x2*x2;
        float dot = q0*x0 + q1*x1 + q2*x2;
        float d2 = (qq + xx) - 2.0f*dot;
        bool hit = d2 < R2;
        unsigned bal = __ballot_sync(0xffffffffu, hit);
        if (firstIdx < 0 && bal) firstIdx = base + __ffs(bal) - 1;
        if (hit){
            int pos = cnt + __popc(bal & ((1u << lane) - 1u));
            if (pos < NS) d_idx[gw*NS + pos] = n;
        }
        cnt += __popc(bal);
        if (cnt >= NS) break;
    }
    if (cnt < NS){
        int f = (firstIdx < 0) ? 0 : firstIdx;
        if (lane >= cnt) d_idx[gw*NS + lane] = f;
    }
}

// ---------------- tensor-core GEMM kernels ----------------
// smem layout (bf16 tiles, padded stride 136 elems = 272 B, conflict-free frag loads)
#define TS   136
#define TBYT (128*TS*2)          // 34816 B per tile
#define G1_AH 0
#define G1_AL (TBYT)
#define G1_BH (2*TBYT)
#define G1_BL (3*TBYT)
#define G1_REL (4*TBYT)          // 3*128 fp32 = 1536 B
#define G1_WR  (4*TBYT + 1536)   // 128*3 fp32 = 1536 B
#define G1_SMEM (4*TBYT + 3072)
#define G2_SC  (4*TBYT)          // 2*128 fp32
#define G2_SMEM (4*TBYT + 1024)

// GEMM1: out0[j][k] (k=row 0..127) = W0(128x131) @ [rel;feat] with K reordered:
// MMA over 128 feature channels (w0 cols 3..130); rel (w0 cols 0..2) in FFMA epilogue.
__global__ void __launch_bounds__(256, 1) kg1(const float* __restrict__ w0,
                                              const float* __restrict__ bxyz){
    extern __shared__ char smx[];
    __nv_bfloat16* Ah = (__nv_bfloat16*)(smx + G1_AH);
    __nv_bfloat16* Al = (__nv_bfloat16*)(smx + G1_AL);
    __nv_bfloat16* Bh = (__nv_bfloat16*)(smx + G1_BH);
    __nv_bfloat16* Bl = (__nv_bfloat16*)(smx + G1_BL);
    float* relS = (float*)(smx + G1_REL);
    float* wrS  = (float*)(smx + G1_WR);

    const int tid = threadIdx.x;
    const int lane = tid & 31, wid = tid >> 5;
    const int g = lane >> 2, tid4 = lane & 3;
    const int m0 = (wid & 3) * 32;          // 2 m16 tiles
    const int warp_n = wid >> 2;
    const int n0 = warp_n * 64;             // 8 n8 tiles
    const int jb = blockIdx.x * 128;

    // W0 -> smem bf16 split (feature part, K reordered)
    for (int e = tid; e < 128*128; e += 256){
        int r = e >> 7, k = e & 127;
        float v = w0[r*131 + 3 + k];
        bsplit(v, Ah[r*TS + k], Al[r*TS + k]);
    }
    for (int e = tid; e < 128*3; e += 256){
        int r = e / 3, d = e - r*3;
        wrS[r*3 + d] = w0[r*131 + d];
    }
    // gather B columns: Bs[j][k] bf16 hi/lo + rel
    {
        int col = tid >> 1, half = tid & 1;
        int j = jb + col;
        int b = j >> 16;
        int m = (j & 65535) >> 5;
        int n = d_idx[j];
        size_t base = ((size_t)(b*NPT + n)) * CF + half*64;
        const uint4* sh = (const uint4*)(d_fh + base);
        const uint4* sl = (const uint4*)(d_fl + base);
        uint4* dh = (uint4*)(Bh + col*TS + half*64);
        uint4* dl = (uint4*)(Bl + col*TS + half*64);
        #pragma unroll
        for (int i = 0; i < 8; i++){ dh[i] = sh[i]; dl[i] = sl[i]; }
        if (half == 0){
            const float* xp = bxyz + (size_t)(b*NPT + n)*3;
            const float* qp = d_nxyz + (size_t)(b*MQ + m)*3;
            relS[col]       = xp[0] - qp[0];
            relS[128 + col] = xp[1] - qp[1];
            relS[256 + col] = xp[2] - qp[2];
        }
    }
    __syncthreads();

    float acc[2][8][4];
    #pragma unroll
    for (int mt = 0; mt < 2; mt++)
        #pragma unroll
        for (int nt = 0; nt < 8; nt++)
            #pragma unroll
            for (int c = 0; c < 4; c++) acc[mt][nt][c] = 0.f;

    #pragma unroll
    for (int ks = 0; ks < 8; ks++){
        const int ko = ks*16 + tid4*2;
        unsigned ah[2][4], al[2][4];
        #pragma unroll
        for (int mt = 0; mt < 2; mt++){
            const __nv_bfloat16* p0 = Ah + (m0 + mt*16 + g)*TS + ko;
            const __nv_bfloat16* p1 = Ah + (m0 + mt*16 + g + 8)*TS + ko;
            ah[mt][0] = *(const unsigned*)p0;
            ah[mt][1] = *(const unsigned*)p1;
            ah[mt][2] = *(const unsigned*)(p0 + 8);
            ah[mt][3] = *(const unsigned*)(p1 + 8);
            const __nv_bfloat16* q0 = Al + (m0 + mt*16 + g)*TS + ko;
            const __nv_bfloat16* q1 = Al + (m0 + mt*16 + g + 8)*TS + ko;
            al[mt][0] = *(const unsigned*)q0;
            al[mt][1] = *(const unsigned*)q1;
            al[mt][2] = *(const unsigned*)(q0 + 8);
            al[mt][3] = *(const unsigned*)(q1 + 8);
        }
        #pragma unroll
        for (int nt = 0; nt < 8; nt++){
            const __nv_bfloat16* pb = Bh + (n0 + nt*8 + g)*TS + ko;
            const __nv_bfloat16* ql = Bl + (n0 + nt*8 + g)*TS + ko;
            unsigned bh0 = *(const unsigned*)pb;
            unsigned bh1 = *(const unsigned*)(pb + 8);
            unsigned bl0 = *(const unsigned*)ql;
            unsigned bl1 = *(const unsigned*)(ql + 8);
            #pragma unroll
            for (int mt = 0; mt < 2; mt++){
                float* a = acc[mt][nt];
                mma_bf16(a[0],a[1],a[2],a[3], ah[mt][0],ah[mt][1],ah[mt][2],ah[mt][3], bh0,bh1);
                mma_bf16(a[0],a[1],a[2],a[3], al[mt][0],al[mt][1],al[mt][2],al[mt][3], bh0,bh1);
                mma_bf16(a[0],a[1],a[2],a[3], ah[mt][0],ah[mt][1],ah[mt][2],ah[mt][3], bl0,bl1);
            }
        }
    }
    __syncthreads();

    float* red = (float*)smx;           // 256 floats (reuses Ah region)
    red[tid] = 0.f;
    __syncthreads();

    float wr[2][2][3];
    #pragma unroll
    for (int mt = 0; mt < 2; mt++)
        #pragma unroll
        for (int rh = 0; rh < 2; rh++){
            int r = m0 + mt*16 + g + rh*8;
            wr[mt][rh][0] = wrS[r*3+0];
            wr[mt][rh][1] = wrS[r*3+1];
            wr[mt][rh][2] = wrS[r*3+2];
        }
    float rs[2][2] = {{0,0},{0,0}}, rq[2][2] = {{0,0},{0,0}};
    #pragma unroll
    for (int nt = 0; nt < 8; nt++){
        int c = n0 + nt*8 + tid4*2;
        float r00 = relS[c],     r01 = relS[c+1];
        float r10 = relS[128+c], r11 = relS[129+c];
        float r20 = relS[256+c], r21 = relS[257+c];
        #pragma unroll
        for (int mt = 0; mt < 2; mt++){
            float* a = acc[mt][nt];
            a[0] += wr[mt][0][0]*r00 + wr[mt][0][1]*r10 + wr[mt][0][2]*r20;
            a[1] += wr[mt][0][0]*r01 + wr[mt][0][1]*r11 + wr[mt][0][2]*r21;
            a[2] += wr[mt][1][0]*r00 + wr[mt][1][1]*r10 + wr[mt][1][2]*r20;
            a[3] += wr[mt][1][0]*r01 + wr[mt][1][1]*r11 + wr[mt][1][2]*r21;
            int r0 = m0 + mt*16 + g, r1 = r0 + 8;
            size_t cb = (size_t)(jb + c) * 128;
            d_out0[cb + r0]       = a[0];
            d_out0[cb + 128 + r0] = a[1];
            d_out0[cb + r1]       = a[2];
            d_out0[cb + 128 + r1] = a[3];
            rs[mt][0] += a[0] + a[1]; rq[mt][0] += a[0]*a[0] + a[1]*a[1];
            rs[mt][1] += a[2] + a[3]; rq[mt][1] += a[2]*a[2] + a[3]*a[3];
        }
    }
    #pragma unroll
    for (int mt = 0; mt < 2; mt++)
        #pragma unroll
        for (int rh = 0; rh < 2; rh++){
            float s = red4sum(rs[mt][rh]);
            float q = red4sum(rq[mt][rh]);
            if (tid4 == 0){
                int r = m0 + mt*16 + g + rh*8;
                atomicAdd(&red[r], s);
                atomicAdd(&red[128 + r], q);
            }
        }
    __syncthreads();
    if (tid < 128){
        atomicAdd(&d_stats[tid],       red[tid]);
        atomicAdd(&d_stats[128 + tid], red[128 + tid]);
    }
}

__global__ void kfm(int which, const float* __restrict__ g, const float* __restrict__ bb){
    int c = threadIdx.x;
    float inv = 1.0f / (float)COLS;
    int so = (which == 0) ? 0 : 256;
    int qo = (which == 0) ? 128 : 512;
    float mean = d_stats[so + c] * inv;
    float var  = d_stats[qo + c] * inv - mean*mean;
    float scl  = g[c] * rsqrtf(var + EPSV);
    if (which == 0){ d_scm0[c] = scl; d_bim0[c] = fmaf(-mean, scl, bb[c]); }
    else           { d_scm1[c] = scl; d_bim1[c] = fmaf(-mean, scl, bb[c]); }
}

// GEMM2: z = W1(256x128) @ relu(bn(out0)); grid (2048, 2); fused stats + max/min pool
__global__ void __launch_bounds__(256, 1) kg2(const float* __restrict__ w1){
    extern __shared__ char smx[];
    __nv_bfloat16* Ah = (__nv_bfloat16*)(smx + G1_AH);
    __nv_bfloat16* Al = (__nv_bfloat16*)(smx + G1_AL);
    __nv_bfloat16* Bh = (__nv_bfloat16*)(smx + G1_BH);
    __nv_bfloat16* Bl = (__nv_bfloat16*)(smx + G1_BL);
    float* scS = (float*)(smx + G2_SC);

    const int tid = threadIdx.x;
    const int lane = tid & 31, wid = tid >> 5;
    const int g = lane >> 2, tid4 = lane & 3;
    const int m0 = (wid & 3) * 32;
    const int warp_n = wid >> 2;
    const int n0 = warp_n * 64;
    const int jb = blockIdx.x * 128;
    const int rowOff = blockIdx.y * 128;

    if (tid < 128){ scS[tid] = d_scm0[tid]; scS[128 + tid] = d_bim0[tid]; }
    __syncthreads();

    for (int e = tid; e < 128*128; e += 256){
        int r = e >> 7, k = e & 127;
        float v = w1[(rowOff + r)*128 + k];
        bsplit(v, Ah[r*TS + k], Al[r*TS + k]);
    }
    for (int e = tid; e < 128*128; e += 256){
        int col = e >> 7, k = e & 127;
        float x = d_out0[(size_t)(jb + col)*128 + k];
        float v = fmaxf(fmaf(scS[k], x, scS[128 + k]), 0.f);
        bsplit(v, Bh[col*TS + k], Bl[col*TS + k]);
    }
    __syncthreads();

    float acc[2][8][4];
    #pragma unroll
    for (int mt = 0; mt < 2; mt++)
        #pragma unroll
        for (int nt = 0; nt < 8; nt++)
            #pragma unroll
            for (int c = 0; c < 4; c++) acc[mt][nt][c] = 0.f;

    #pragma unroll
    for (int ks = 0; ks < 8; ks++){
        const int ko = ks*16 + tid4*2;
        unsigned ah[2][4], al[2][4];
        #pragma unroll
        for (int mt = 0; mt < 2; mt++){
            const __nv_bfloat16* p0 = Ah + (m0 + mt*16 + g)*TS + ko;
            const __nv_bfloat16* p1 = Ah + (m0 + mt*16 + g + 8)*TS + ko;
            ah[mt][0] = *(const unsigned*)p0;
            ah[mt][1] = *(const unsigned*)p1;
            ah[mt][2] = *(const unsigned*)(p0 + 8);
            ah[mt][3] = *(const unsigned*)(p1 + 8);
            const __nv_bfloat16* q0 = Al + (m0 + mt*16 + g)*TS + ko;
            const __nv_bfloat16* q1 = Al + (m0 + mt*16 + g + 8)*TS + ko;
            al[mt][0] = *(const unsigned*)q0;
            al[mt][1] = *(const unsigned*)q1;
            al[mt][2] = *(const unsigned*)(q0 + 8);
            al[mt][3] = *(const unsigned*)(q1 + 8);
        }
        #pragma unroll
        for (int nt = 0; nt < 8; nt++){
            const __nv_bfloat16* pb = Bh + (n0 + nt*8 + g)*TS + ko;
            const __nv_bfloat16* ql = Bl + (n0 + nt*8 + g)*TS + ko;
            unsigned bh0 = *(const unsigned*)pb;
            unsigned bh1 = *(const unsigned*)(pb + 8);
            unsigned bl0 = *(const unsigned*)ql;
            unsigned bl1 = *(const unsigned*)(ql + 8);
            #pragma unroll
            for (int mt = 0; mt < 2; mt++){
                float* a = acc[mt][nt];
                mma_bf16(a[0],a[1],a[2],a[3], ah[mt][0],ah[mt][1],ah[mt][2],ah[mt][3], bh0,bh1);
                mma_bf16(a[0],a[1],a[2],a[3], al[mt][0],al[mt][1],al[mt][2],al[mt][3], bh0,bh1);
                mma_bf16(a[0],a[1],a[2],a[3], ah[mt][0],ah[mt][1],ah[mt][2],ah[mt][3], bl0,bl1);
            }
        }
    }
    __syncthreads();

    float* red = (float*)smx;
    red[tid] = 0.f;
    __syncthreads();

    float rs[2][2] = {{0,0},{0,0}}, rq[2][2] = {{0,0},{0,0}};
    float mx[2][2][2], mn[2][2][2];
    #pragma unroll
    for (int mt = 0; mt < 2; mt++)
        #pragma unroll
        for (int rh = 0; rh < 2; rh++)
            #pragma unroll
            for (int qi = 0; qi < 2; qi++){ mx[mt][rh][qi] = -3.4e38f; mn[mt][rh][qi] = 3.4e38f; }

    #pragma unroll
    for (int nt = 0; nt < 8; nt++){
        int qi = nt >> 2;
        #pragma unroll
        for (int mt = 0; mt < 2; mt++){
            float* a = acc[mt][nt];
            rs[mt][0] += a[0] + a[1]; rq[mt][0] += a[0]*a[0] + a[1]*a[1];
            rs[mt][1] += a[2] + a[3]; rq[mt][1] += a[2]*a[2] + a[3]*a[3];
            mx[mt][0][qi] = fmaxf(mx[mt][0][qi], fmaxf(a[0], a[1]));
            mn[mt][0][qi] = fminf(mn[mt][0][qi], fminf(a[0], a[1]));
            mx[mt][1][qi] = fmaxf(mx[mt][1][qi], fmaxf(a[2], a[3]));
            mn[mt][1][qi] = fminf(mn[mt][1][qi], fminf(a[2], a[3]));
        }
    }
    #pragma unroll
    for (int mt = 0; mt < 2; mt++)
        #pragma unroll
        for (int rh = 0; rh < 2; rh++){
            float s = red4sum(rs[mt][rh]);
            float q = red4sum(rq[mt][rh]);
            #pragma unroll
            for (int qi = 0; qi < 2; qi++){
                float vmx = red4max(mx[mt][rh][qi]);
                float vmn = red4min(mn[mt][rh][qi]);
                if (tid4 == 0){
                    int rg = rowOff + m0 + mt*16 + g + rh*8;
                    int qg = blockIdx.x*4 + warp_n*2 + qi;
                    d_pmax[(size_t)qg*256 + rg] = vmx;
                    d_pmin[(size_t)qg*256 + rg] = vmn;
                }
            }
            if (tid4 == 0){
                int rl = m0 + mt*16 + g + rh*8;
                atomicAdd(&red[rl], s);
                atomicAdd(&red[128 + rl], q);
            }
        }
    __syncthreads();
    if (tid < 128){
        atomicAdd(&d_stats[256 + rowOff + tid], red[tid]);
        atomicAdd(&d_stats[512 + rowOff + tid], red[128 + tid]);
    }
}

// final: out[p][c] = relu(s*pooled + t), pooled = max if s>=0 else min
__global__ void kfin(float* __restrict__ out){
    int c = threadIdx.x;
    int p = blockIdx.x;
    float s = d_scm1[c], t = d_bim1[c];
    float v = (s >= 0.f) ? d_pmax[(size_t)p*256 + c] : d_pmin[(size_t)p*256 + c];
    out[(size_t)p*256 + c] = fmaxf(fmaf(s, v, t), 0.f);
}

// ---------------- launch ----------------
extern "C" void kernel_launch(void* const* d_in, const int* in_sizes, int n_in,
                              void* d_out, int out_size){
    (void)in_sizes; (void)n_in; (void)out_size;
    const float* ffps = (const float*)d_in[0];
    const float* bxyz = (const float*)d_in[1];
    const float* bfeat= (const float*)d_in[2];
    const float* sw0  = (const float*)d_in[3];
    const float* sg0  = (const float*)d_in[4];
    const float* sb0  = (const float*)d_in[5];
    const float* sw1  = (const float*)d_in[6];
    const float* sg1  = (const float*)d_in[7];
    const float* sb1  = (const float*)d_in[8];
    const float* mw0  = (const float*)d_in[9];
    const float* mg0  = (const float*)d_in[10];
    const float* mb0  = (const float*)d_in[11];
    const float* mw1  = (const float*)d_in[12];
    const float* mg1  = (const float*)d_in[13];
    const float* mb1  = (const float*)d_in[14];
    float* out = (float*)d_out;

    cudaFuncSetAttribute(kg1, cudaFuncAttributeMaxDynamicSharedMemorySize, G1_SMEM);
    cudaFuncSetAttribute(kg2, cudaFuncAttributeMaxDynamicSharedMemorySize, G2_SMEM);

    kzero<<<3, 256>>>();
    ks1<<<PTOT/256, 256>>>(ffps, sw0);
    kstat<<<64, 256>>>(0, sg0, sb0);
    ks2<<<PTOT/256, 256>>>(sw1);
    kstat<<<3, 256>>>(1, sg1, sb1);
    ks3<<<PTOT/256, 256>>>();
    ktr<<<dim3(NPT/32, CF/32, BQ), dim3(32, 8)>>>(bfeat);
    kballq<<<PTOT/8, 256>>>(bxyz);
    kg1<<<COLS/128, 256, G1_SMEM>>>(mw0, bxyz);
    kfm<<<1, 128>>>(0, mg0, mb0);
    kg2<<<dim3(COLS/128, 2), 256, G2_SMEM>>>(mw1);
    kfm<<<1, 256>>>(1, mg1, mb1);
    kfin<<<PTOT, 256>>>(out);
}

// round 11
// speedup vs baseline: 4.3112x; 1.5632x over previous
#include <cuda_runtime.h>
#include <cuda_bf16.h>
#include <cstdint>

#define BQ   4
#define NPT  16384
#define MQ   2048
#define CF   128
#define NS   32
#define PTOT (BQ*MQ)        // 8192 query points
#define COLS (PTOT*NS)      // 262144 GEMM columns
#define R2   9.0f
#define EPSV 1e-5f

// ---------------- static scratch (allocation-free rule) ----------------
__device__ float d_h0[64*PTOT];
__device__ float d_h1[3*PTOT];
__device__ float d_nxyz[PTOT*3];
__device__ __nv_bfloat16 d_fh[(size_t)BQ*NPT*CF];   // features hi  [b][n][c]
__device__ __nv_bfloat16 d_fl[(size_t)BQ*NPT*CF];   // features lo
__device__ __nv_bfloat16 d_w0h[128*128], d_w0l[128*128];  // w0 feature part, pre-split
__device__ __nv_bfloat16 d_w1h[256*128], d_w1l[256*128];  // w1, pre-split
__device__ int   d_idx[COLS];
__device__ float d_out0[(size_t)COLS*128];          // pre-BN layer-0 acts, [j][k]
__device__ float d_pmax[(size_t)PTOT*256];          // [q][c]
__device__ float d_pmin[(size_t)PTOT*256];
__device__ float d_stats[768];
__device__ float d_sc0[64], d_bi0[64], d_sc1[3], d_bi1[3];
__device__ float d_scm0[128], d_bim0[128], d_scm1[256], d_bim1[256];

// ---------------- helpers ----------------
__device__ __forceinline__ uint32_t smem_u32(const void* p){
    uint32_t a;
    asm("{ .reg .u64 t; cvta.to.shared.u64 t, %1; cvt.u32.u64 %0, t; }" : "=r"(a) : "l"(p));
    return a;
}
__device__ __forceinline__ void bsplit(float x, __nv_bfloat16& h, __nv_bfloat16& l){
    h = __float2bfloat16(x);
    l = __float2bfloat16(x - __bfloat162float(h));
}
__device__ __forceinline__ void mma_bf16(float& c0, float& c1, float& c2, float& c3,
                                         unsigned a0, unsigned a1, unsigned a2, unsigned a3,
                                         unsigned b0, unsigned b1){
    asm volatile("mma.sync.aligned.m16n8k16.row.col.f32.bf16.bf16.f32 "
        "{%0,%1,%2,%3}, {%4,%5,%6,%7}, {%8,%9}, {%0,%1,%2,%3};"
        : "+f"(c0), "+f"(c1), "+f"(c2), "+f"(c3)
        : "r"(a0), "r"(a1), "r"(a2), "r"(a3), "r"(b0), "r"(b1));
}
__device__ __forceinline__ void ldsm4(unsigned& r0, unsigned& r1, unsigned& r2, unsigned& r3, uint32_t a){
    asm volatile("ldmatrix.sync.aligned.m8n8.x4.shared.b16 {%0,%1,%2,%3}, [%4];"
        : "=r"(r0), "=r"(r1), "=r"(r2), "=r"(r3) : "r"(a));
}
__device__ __forceinline__ void ldsm2(unsigned& r0, unsigned& r1, uint32_t a){
    asm volatile("ldmatrix.sync.aligned.m8n8.x2.shared.b16 {%0,%1}, [%2];"
        : "=r"(r0), "=r"(r1) : "r"(a));
}
__device__ __forceinline__ void cpa16(uint32_t dst, const void* src){
    asm volatile("cp.async.cg.shared.global [%0], [%1], 16;" :: "r"(dst), "l"(src));
}
__device__ __forceinline__ void cpwait(){
    asm volatile("cp.async.commit_group;\n\tcp.async.wait_group 0;" ::: "memory");
}
__device__ __forceinline__ float red4sum(float v){
    v += __shfl_xor_sync(0xffffffffu, v, 1, 4);
    v += __shfl_xor_sync(0xffffffffu, v, 2, 4);
    return v;
}
__device__ __forceinline__ float red4max(float v){
    v = fmaxf(v, __shfl_xor_sync(0xffffffffu, v, 1, 4));
    v = fmaxf(v, __shfl_xor_sync(0xffffffffu, v, 2, 4));
    return v;
}
__device__ __forceinline__ float red4min(float v){
    v = fminf(v, __shfl_xor_sync(0xffffffffu, v, 1, 4));
    v = fminf(v, __shfl_xor_sync(0xffffffffu, v, 2, 4));
    return v;
}
__device__ __forceinline__ void packsplit8(const float* f, uint4& vh, uint4& vl){
    unsigned ph[4], pl[4];
    #pragma unroll
    for (int p = 0; p < 4; p++){
        __nv_bfloat16 h0, l0, h1, l1;
        bsplit(f[2*p],   h0, l0);
        bsplit(f[2*p+1], h1, l1);
        ph[p] = ((unsigned)__bfloat16_as_ushort(h1) << 16) | __bfloat16_as_ushort(h0);
        pl[p] = ((unsigned)__bfloat16_as_ushort(l1) << 16) | __bfloat16_as_ushort(l0);
    }
    vh = make_uint4(ph[0], ph[1], ph[2], ph[3]);
    vl = make_uint4(pl[0], pl[1], pl[2], pl[3]);
}

// ---------------- small kernels ----------------
__global__ void kzero(){
    int i = blockIdx.x*blockDim.x + threadIdx.x;
    if (i < 768) d_stats[i] = 0.f;
}

__global__ void kwprep(const float* __restrict__ w0, const float* __restrict__ w1){
    int i = blockIdx.x*256 + threadIdx.x;
    if (i < 128*128){
        int r = i >> 7, k = i & 127;
        __nv_bfloat16 h, l; bsplit(w0[r*131 + 3 + k], h, l);
        d_w0h[i] = h; d_w0l[i] = l;
    } else if (i < 128*128 + 256*128){
        int j = i - 128*128;
        __nv_bfloat16 h, l; bsplit(w1[j], h, l);
        d_w1h[j] = h; d_w1l[j] = l;
    }
}

__global__ void ks1(const float* __restrict__ ffps, const float* __restrict__ w0){
    int p = blockIdx.x*blockDim.x + threadIdx.x;
    float f0 = ffps[p*3+0], f1 = ffps[p*3+1], f2 = ffps[p*3+2];
    #pragma unroll 4
    for (int c = 0; c < 64; c++){
        float v = w0[c*3+0]*f0 + w0[c*3+1]*f1 + w0[c*3+2]*f2;
        d_h0[c*PTOT + p] = v;
    }
}

__global__ void kstat(int which, const float* __restrict__ g, const float* __restrict__ bb){
    __shared__ float ss[256], sq[256];
    int c = blockIdx.x;
    const float* buf = (which == 0 ? d_h0 : d_h1) + c*PTOT;
    float s = 0.f, q = 0.f;
    for (int i = threadIdx.x; i < PTOT; i += 256){
        float v = buf[i]; s += v; q = fmaf(v, v, q);
    }
    ss[threadIdx.x] = s; sq[threadIdx.x] = q; __syncthreads();
    for (int o = 128; o > 0; o >>= 1){
        if (threadIdx.x < o){
            ss[threadIdx.x] += ss[threadIdx.x+o];
            sq[threadIdx.x] += sq[threadIdx.x+o];
        }
        __syncthreads();
    }
    if (threadIdx.x == 0){
        float mean = ss[0] / (float)PTOT;
        float var  = sq[0] / (float)PTOT - mean*mean;
        float scl  = g[c] * rsqrtf(var + EPSV);
        if (which == 0){ d_sc0[c] = scl; d_bi0[c] = fmaf(-mean, scl, bb[c]); }
        else           { d_sc1[c] = scl; d_bi1[c] = fmaf(-mean, scl, bb[c]); }
    }
}

__global__ void ks2(const float* __restrict__ w1){
    int p = blockIdx.x*blockDim.x + threadIdx.x;
    float a0 = 0.f, a1 = 0.f, a2 = 0.f;
    #pragma unroll 4
    for (int c = 0; c < 64; c++){
        float v = fmaxf(fmaf(d_sc0[c], d_h0[c*PTOT + p], d_bi0[c]), 0.f);
        a0 = fmaf(w1[c],       v, a0);
        a1 = fmaf(w1[64 + c],  v, a1);
        a2 = fmaf(w1[128 + c], v, a2);
    }
    d_h1[p] = a0; d_h1[PTOT + p] = a1; d_h1[2*PTOT + p] = a2;
}

__global__ void ks3(){
    int p = blockIdx.x*blockDim.x + threadIdx.x;
    #pragma unroll
    for (int o = 0; o < 3; o++)
        d_nxyz[p*3 + o] = fmaxf(fmaf(d_sc1[o], d_h1[o*PTOT + p], d_bi1[o]), 0.f);
}

__global__ void ktr(const float* __restrict__ feat){
    __shared__ float t[32][33];
    int b = blockIdx.z, n0 = blockIdx.x*32, c0 = blockIdx.y*32;
    for (int i = threadIdx.y; i < 32; i += 8)
        t[i][threadIdx.x] = feat[((size_t)b*CF + (c0+i))*NPT + n0 + threadIdx.x];
    __syncthreads();
    for (int i = threadIdx.y; i < 32; i += 8){
        float v = t[threadIdx.x][i];
        __nv_bfloat16 h, l; bsplit(v, h, l);
        size_t o = ((size_t)b*NPT + (n0+i))*CF + c0 + threadIdx.x;
        d_fh[o] = h; d_fl[o] = l;
    }
}

__global__ void kballq(const float* __restrict__ bxyz){
    int gw = (blockIdx.x*blockDim.x + threadIdx.x) >> 5;
    int lane = threadIdx.x & 31;
    int b = gw >> 11;
    float q0 = d_nxyz[gw*3+0], q1 = d_nxyz[gw*3+1], q2 = d_nxyz[gw*3+2];
    float qq = q0*q0 + q1*q1 + q2*q2;
    const float* xb = bxyz + (size_t)b*NPT*3;
    int cnt = 0, firstIdx = -1;
    for (int base = 0; base < NPT; base += 32){
        int n = base + lane;
        float x0 = xb[n*3+0], x1 = xb[n*3+1], x2 = xb[n*3+2];
        float xx = x0*x0 + x1*x1 + x2*x2;
        float dot = q0*x0 + q1*x1 + q2*x2;
        float d2 = (qq + xx) - 2.0f*dot;
        bool hit = d2 < R2;
        unsigned bal = __ballot_sync(0xffffffffu, hit);
        if (firstIdx < 0 && bal) firstIdx = base + __ffs(bal) - 1;
        if (hit){
            int pos = cnt + __popc(bal & ((1u << lane) - 1u));
            if (pos < NS) d_idx[gw*NS + pos] = n;
        }
        cnt += __popc(bal);
        if (cnt >= NS) break;
    }
    if (cnt < NS){
        int f = (firstIdx < 0) ? 0 : firstIdx;
        if (lane >= cnt) d_idx[gw*NS + lane] = f;
    }
}

// ---------------- GEMM kernels (HMMA + ldmatrix + cp.async) ----------------
// padded bf16 tiles: row stride 272 B (136 bf16) — conflict-free for ldmatrix
#define TSB  272
// kg1 smem offsets
#define K1_AH 0
#define K1_AL 34816
#define K1_BH 69632
#define K1_BL 104448
#define K1_REL 139264
#define K1_SMEM (139264 + 1536)
// kg2 smem offsets (A = 256 rows)
#define K2_AH 0
#define K2_AL 69632
#define K2_BH 139264
#define K2_BL 174080
#define K2_SC 208896
#define K2_SMEM (208896 + 1024)

// GEMM1: 128x128 tile of out0 = W0feat(128x128) @ gathered feats; rel via FFMA epilogue.
__global__ void __launch_bounds__(256, 1) kg1(const float* __restrict__ w0,
                                              const float* __restrict__ bxyz){
    extern __shared__ char smx[];
    float* relS = (float*)(smx + K1_REL);
    const int tid = threadIdx.x;
    const int lane = tid & 31, wid = tid >> 5;
    const int g = lane >> 2, tid4 = lane & 3;
    const int m0 = (wid & 3) * 32;          // 2 m16 tiles
    const int wn = wid >> 2;
    const int n0 = wn * 64;                 // 8 n8 tiles
    const int jb = blockIdx.x * 128;
    uint32_t sb = smem_u32(smx);

    // A fill: pre-split w0 via cp.async (16B chunks)
    for (int e = tid; e < 2048; e += 256){
        int r = e >> 4, kc = e & 15;
        uint32_t d = sb + K1_AH + r*TSB + kc*16;
        cpa16(d, d_w0h + r*128 + kc*8);
        cpa16(d + (K1_AL - K1_AH), d_w0l + r*128 + kc*8);
    }
    // B gather via cp.async + rel
    {
        int col = tid >> 1, half = tid & 1;
        int j = jb + col;
        int b = j >> 16;
        int m = (j & 65535) >> 5;
        int n = d_idx[j];
        size_t base = ((size_t)(b*NPT + n))*CF + half*64;
        uint32_t db = sb + K1_BH + col*TSB + half*128;
        #pragma unroll
        for (int i = 0; i < 8; i++){
            cpa16(db + i*16, d_fh + base + i*8);
            cpa16(db + (K1_BL - K1_BH) + i*16, d_fl + base + i*8);
        }
        if (half == 0){
            const float* xp = bxyz + (size_t)(b*NPT + n)*3;
            const float* qp = d_nxyz + (size_t)(b*MQ + m)*3;
            relS[col]       = xp[0] - qp[0];
            relS[128 + col] = xp[1] - qp[1];
            relS[256 + col] = xp[2] - qp[2];
        }
    }
    cpwait();
    __syncthreads();

    // fragment base addresses
    uint32_t aH[2], aL[2], bHa[8], bLa[8];
    #pragma unroll
    for (int mt = 0; mt < 2; mt++){
        int row = m0 + mt*16 + (lane & 15);
        uint32_t off = row*TSB + ((lane & 16) ? 16 : 0);
        aH[mt] = sb + K1_AH + off;
        aL[mt] = sb + K1_AL + off;
    }
    #pragma unroll
    for (int nt = 0; nt < 8; nt++){
        int row = n0 + nt*8 + (lane & 7);
        uint32_t off = row*TSB + (((lane >> 3) & 1) << 4);
        bHa[nt] = sb + K1_BH + off;
        bLa[nt] = sb + K1_BL + off;
    }

    float acc[2][8][4];
    #pragma unroll
    for (int mt = 0; mt < 2; mt++)
        #pragma unroll
        for (int nt = 0; nt < 8; nt++)
            #pragma unroll
            for (int c = 0; c < 4; c++) acc[mt][nt][c] = 0.f;

    #pragma unroll
    for (int ks = 0; ks < 8; ks++){
        const uint32_t kd = ks*32;
        unsigned ah[2][4], al[2][4];
        #pragma unroll
        for (int mt = 0; mt < 2; mt++){
            ldsm4(ah[mt][0], ah[mt][1], ah[mt][2], ah[mt][3], aH[mt] + kd);
            ldsm4(al[mt][0], al[mt][1], al[mt][2], al[mt][3], aL[mt] + kd);
        }
        #pragma unroll
        for (int nt = 0; nt < 8; nt++){
            unsigned b0, b1, c0, c1;
            ldsm2(b0, b1, bHa[nt] + kd);
            ldsm2(c0, c1, bLa[nt] + kd);
            #pragma unroll
            for (int mt = 0; mt < 2; mt++){
                float* a = acc[mt][nt];
                mma_bf16(a[0],a[1],a[2],a[3], ah[mt][0],ah[mt][1],ah[mt][2],ah[mt][3], b0,b1);
                mma_bf16(a[0],a[1],a[2],a[3], al[mt][0],al[mt][1],al[mt][2],al[mt][3], b0,b1);
                mma_bf16(a[0],a[1],a[2],a[3], ah[mt][0],ah[mt][1],ah[mt][2],ah[mt][3], c0,c1);
            }
        }
    }
    __syncthreads();

    float* red = (float*)smx;           // 256 floats
    red[tid] = 0.f;
    __syncthreads();

    float wr[2][2][3];
    #pragma unroll
    for (int mt = 0; mt < 2; mt++)
        #pragma unroll
        for (int rh = 0; rh < 2; rh++){
            int r = m0 + mt*16 + g + rh*8;
            wr[mt][rh][0] = __ldg(&w0[r*131+0]);
            wr[mt][rh][1] = __ldg(&w0[r*131+1]);
            wr[mt][rh][2] = __ldg(&w0[r*131+2]);
        }
    float rs[2][2] = {{0,0},{0,0}}, rq[2][2] = {{0,0},{0,0}};
    #pragma unroll
    for (int nt = 0; nt < 8; nt++){
        int c = n0 + nt*8 + tid4*2;
        float r00 = relS[c],     r01 = relS[c+1];
        float r10 = relS[128+c], r11 = relS[129+c];
        float r20 = relS[256+c], r21 = relS[257+c];
        #pragma unroll
        for (int mt = 0; mt < 2; mt++){
            float* a = acc[mt][nt];
            a[0] += wr[mt][0][0]*r00 + wr[mt][0][1]*r10 + wr[mt][0][2]*r20;
            a[1] += wr[mt][0][0]*r01 + wr[mt][0][1]*r11 + wr[mt][0][2]*r21;
            a[2] += wr[mt][1][0]*r00 + wr[mt][1][1]*r10 + wr[mt][1][2]*r20;
            a[3] += wr[mt][1][0]*r01 + wr[mt][1][1]*r11 + wr[mt][1][2]*r21;
            int r0 = m0 + mt*16 + g, r1 = r0 + 8;
            size_t cb = (size_t)(jb + c) * 128;
            d_out0[cb + r0]       = a[0];
            d_out0[cb + 128 + r0] = a[1];
            d_out0[cb + r1]       = a[2];
            d_out0[cb + 128 + r1] = a[3];
            rs[mt][0] += a[0] + a[1]; rq[mt][0] += a[0]*a[0] + a[1]*a[1];
            rs[mt][1] += a[2] + a[3]; rq[mt][1] += a[2]*a[2] + a[3]*a[3];
        }
    }
    #pragma unroll
    for (int mt = 0; mt < 2; mt++)
        #pragma unroll
        for (int rh = 0; rh < 2; rh++){
            float s = red4sum(rs[mt][rh]);
            float q = red4sum(rq[mt][rh]);
            if (tid4 == 0){
                int r = m0 + mt*16 + g + rh*8;
                atomicAdd(&red[r], s);
                atomicAdd(&red[128 + r], q);
            }
        }
    __syncthreads();
    if (tid < 128){
        atomicAdd(&d_stats[tid],       red[tid]);
        atomicAdd(&d_stats[128 + tid], red[128 + tid]);
    }
}

__global__ void kfm(int which, const float* __restrict__ g, const float* __restrict__ bb){
    int c = threadIdx.x;
    float inv = 1.0f / (float)COLS;
    int so = (which == 0) ? 0 : 256;
    int qo = (which == 0) ? 128 : 512;
    float mean = d_stats[so + c] * inv;
    float var  = d_stats[qo + c] * inv - mean*mean;
    float scl  = g[c] * rsqrtf(var + EPSV);
    if (which == 0){ d_scm0[c] = scl; d_bim0[c] = fmaf(-mean, scl, bb[c]); }
    else           { d_scm1[c] = scl; d_bim1[c] = fmaf(-mean, scl, bb[c]); }
}

// GEMM2: all 256 output rows in one pass; fused BN+relu on load, stats + max/min pool.
__global__ void __launch_bounds__(256, 1) kg2(){
    extern __shared__ char smx[];
    float* scS = (float*)(smx + K2_SC);     // [0:128) scale, [128:256) bias
    const int tid = threadIdx.x;
    const int lane = tid & 31, wid = tid >> 5;
    const int g = lane >> 2, tid4 = lane & 3;
    const int m0 = (wid & 3) * 64;          // 4 m16 tiles over 256 rows
    const int wn = wid >> 2;
    const int n0 = wn * 64;                 // 8 n8 tiles
    const int jb = blockIdx.x * 128;
    uint32_t sb = smem_u32(smx);

    if (tid < 128){ scS[tid] = d_scm0[tid]; scS[128 + tid] = d_bim0[tid]; }

    // A fill: pre-split w1 via cp.async (256 rows)
    for (int e = tid; e < 4096; e += 256){
        int r = e >> 4, kc = e & 15;
        uint32_t d = sb + K2_AH + r*TSB + kc*16;
        cpa16(d, d_w1h + r*128 + kc*8);
        cpa16(d + (K2_AL - K2_AH), d_w1l + r*128 + kc*8);
    }
    __syncthreads();                        // scS visible

    // B fill: load out0 col, BN+relu, split, STS.128
    {
        int col = tid >> 1, half = tid & 1;
        const float* src = d_out0 + (size_t)(jb + col)*128 + half*64;
        char* bh = smx + K2_BH + col*TSB + half*128;
        char* bl = smx + K2_BL + col*TSB + half*128;
        #pragma unroll
        for (int kc = 0; kc < 8; kc++){
            float4 x0 = *(const float4*)(src + kc*8);
            float4 x1 = *(const float4*)(src + kc*8 + 4);
            float f[8] = {x0.x, x0.y, x0.z, x0.w, x1.x, x1.y, x1.z, x1.w};
            #pragma unroll
            for (int i = 0; i < 8; i++){
                int k = half*64 + kc*8 + i;
                f[i] = fmaxf(fmaf(scS[k], f[i], scS[128 + k]), 0.f);
            }
            uint4 vh, vl; packsplit8(f, vh, vl);
            *(uint4*)(bh + kc*16) = vh;
            *(uint4*)(bl + kc*16) = vl;
        }
    }
    cpwait();
    __syncthreads();

    uint32_t aH[4], aL[4], bHa[8], bLa[8];
    #pragma unroll
    for (int mt = 0; mt < 4; mt++){
        int row = m0 + mt*16 + (lane & 15);
        uint32_t off = row*TSB + ((lane & 16) ? 16 : 0);
        aH[mt] = sb + K2_AH + off;
        aL[mt] = sb + K2_AL + off;
    }
    #pragma unroll
    for (int nt = 0; nt < 8; nt++){
        int row = n0 + nt*8 + (lane & 7);
        uint32_t off = row*TSB + (((lane >> 3) & 1) << 4);
        bHa[nt] = sb + K2_BH + off;
        bLa[nt] = sb + K2_BL + off;
    }

    float acc[4][8][4];
    #pragma unroll
    for (int mt = 0; mt < 4; mt++)
        #pragma unroll
        for (int nt = 0; nt < 8; nt++)
            #pragma unroll
            for (int c = 0; c < 4; c++) acc[mt][nt][c] = 0.f;

    #pragma unroll
    for (int ks = 0; ks < 8; ks++){
        const uint32_t kd = ks*32;
        unsigned ah[4][4], al[4][4];
        #pragma unroll
        for (int mt = 0; mt < 4; mt++){
            ldsm4(ah[mt][0], ah[mt][1], ah[mt][2], ah[mt][3], aH[mt] + kd);
            ldsm4(al[mt][0], al[mt][1], al[mt][2], al[mt][3], aL[mt] + kd);
        }
        #pragma unroll
        for (int nt = 0; nt < 8; nt++){
            unsigned b0, b1, c0, c1;
            ldsm2(b0, b1, bHa[nt] + kd);
            ldsm2(c0, c1, bLa[nt] + kd);
            #pragma unroll
            for (int mt = 0; mt < 4; mt++){
                float* a = acc[mt][nt];
                mma_bf16(a[0],a[1],a[2],a[3], ah[mt][0],ah[mt][1],ah[mt][2],ah[mt][3], b0,b1);
                mma_bf16(a[0],a[1],a[2],a[3], al[mt][0],al[mt][1],al[mt][2],al[mt][3], b0,b1);
                mma_bf16(a[0],a[1],a[2],a[3], ah[mt][0],ah[mt][1],ah[mt][2],ah[mt][3], c0,c1);
            }
        }
    }
    __syncthreads();

    float* red = (float*)smx;               // 512 floats
    red[tid] = 0.f;
    red[256 + tid] = 0.f;
    __syncthreads();

    float rs[4][2], rq[4][2];
    float mx[4][2][2], mn[4][2][2];
    #pragma unroll
    for (int mt = 0; mt < 4; mt++)
        #pragma unroll
        for (int rh = 0; rh < 2; rh++){
            rs[mt][rh] = 0.f; rq[mt][rh] = 0.f;
            #pragma unroll
            for (int qi = 0; qi < 2; qi++){ mx[mt][rh][qi] = -3.4e38f; mn[mt][rh][qi] = 3.4e38f; }
        }
    #pragma unroll
    for (int nt = 0; nt < 8; nt++){
        int qi = nt >> 2;
        #pragma unroll
        for (int mt = 0; mt < 4; mt++){
            float* a = acc[mt][nt];
            rs[mt][0] += a[0] + a[1]; rq[mt][0] += a[0]*a[0] + a[1]*a[1];
            rs[mt][1] += a[2] + a[3]; rq[mt][1] += a[2]*a[2] + a[3]*a[3];
            mx[mt][0][qi] = fmaxf(mx[mt][0][qi], fmaxf(a[0], a[1]));
            mn[mt][0][qi] = fminf(mn[mt][0][qi], fminf(a[0], a[1]));
            mx[mt][1][qi] = fmaxf(mx[mt][1][qi], fmaxf(a[2], a[3]));
            mn[mt][1][qi] = fminf(mn[mt][1][qi], fminf(a[2], a[3]));
        }
    }
    #pragma unroll
    for (int mt = 0; mt < 4; mt++)
        #pragma unroll
        for (int rh = 0; rh < 2; rh++){
            float s = red4sum(rs[mt][rh]);
            float q = red4sum(rq[mt][rh]);
            int rg = m0 + mt*16 + g + rh*8;
            #pragma unroll
            for (int qi = 0; qi < 2; qi++){
                float vmx = red4max(mx[mt][rh][qi]);
                float vmn = red4min(mn[mt][rh][qi]);
                if (tid4 == 0){
                    int qg = blockIdx.x*4 + wn*2 + qi;
                    d_pmax[(size_t)qg*256 + rg] = vmx;
                    d_pmin[(size_t)qg*256 + rg] = vmn;
                }
            }
            if (tid4 == 0){
                atomicAdd(&red[rg], s);
                atomicAdd(&red[256 + rg], q);
            }
        }
    __syncthreads();
    atomicAdd(&d_stats[256 + tid], red[tid]);
    atomicAdd(&d_stats[512 + tid], red[256 + tid]);
}

// final: out[p][c] = relu(s*pooled + t), pooled = max if s>=0 else min
__global__ void kfin(float* __restrict__ out){
    int c = threadIdx.x;
    int p = blockIdx.x;
    float s = d_scm1[c], t = d_bim1[c];
    float v = (s >= 0.f) ? d_pmax[(size_t)p*256 + c] : d_pmin[(size_t)p*256 + c];
    out[(size_t)p*256 + c] = fmaxf(fmaf(s, v, t), 0.f);
}

// ---------------- launch ----------------
extern "C" void kernel_launch(void* const* d_in, const int* in_sizes, int n_in,
                              void* d_out, int out_size){
    (void)in_sizes; (void)n_in; (void)out_size;
    const float* ffps = (const float*)d_in[0];
    const float* bxyz = (const float*)d_in[1];
    const float* bfeat= (const float*)d_in[2];
    const float* sw0  = (const float*)d_in[3];
    const float* sg0  = (const float*)d_in[4];
    const float* sb0  = (const float*)d_in[5];
    const float* sw1  = (const float*)d_in[6];
    const float* sg1  = (const float*)d_in[7];
    const float* sb1  = (const float*)d_in[8];
    const float* mw0  = (const float*)d_in[9];
    const float* mg0  = (const float*)d_in[10];
    const float* mb0  = (const float*)d_in[11];
    const float* mw1  = (const float*)d_in[12];
    const float* mg1  = (const float*)d_in[13];
    const float* mb1  = (const float*)d_in[14];
    float* out = (float*)d_out;

    cudaFuncSetAttribute(kg1, cudaFuncAttributeMaxDynamicSharedMemorySize, K1_SMEM);
    cudaFuncSetAttribute(kg2, cudaFuncAttributeMaxDynamicSharedMemorySize, K2_SMEM);

    kzero<<<3, 256>>>();
    kwprep<<<(128*128 + 256*128 + 255)/256, 256>>>(mw0, mw1);
    ks1<<<PTOT/256, 256>>>(ffps, sw0);
    kstat<<<64, 256>>>(0, sg0, sb0);
    ks2<<<PTOT/256, 256>>>(sw1);
    kstat<<<3, 256>>>(1, sg1, sb1);
    ks3<<<PTOT/256, 256>>>();
    ktr<<<dim3(NPT/32, CF/32, BQ), dim3(32, 8)>>>(bfeat);
    kballq<<<PTOT/8, 256>>>(bxyz);
    kg1<<<COLS/128, 256, K1_SMEM>>>(mw0, bxyz);
    kfm<<<1, 128>>>(0, mg0, mb0);
    kg2<<<COLS/128, 256, K2_SMEM>>>();
    kfm<<<1, 256>>>(1, mg1, mb1);
    kfin<<<PTOT, 256>>>(out);
}

// round 12
// speedup vs baseline: 4.5126x; 1.0467x over previous
#include <cuda_runtime.h>
#include <cuda_fp16.h>
#include <cstdint>

#define BQ   4
#define NPT  16384
#define MQ   2048
#define CF   128
#define NS   32
#define PTOT (BQ*MQ)        // 8192 query points
#define COLS (PTOT*NS)      // 262144 GEMM columns
#define R2   9.0f
#define EPSV 1e-5f

// ---------------- static scratch (allocation-free rule) ----------------
__device__ float d_h0[64*PTOT];
__device__ float d_h1[3*PTOT];
__device__ float d_nxyz[PTOT*3];
__device__ __half d_fh[(size_t)BQ*NPT*CF];          // features fp16 [b][n][c]
__device__ __half d_w0h[128*128], d_w0l[128*128];   // w0 feature part hi/lo fp16
__device__ __half d_w1h[256*128], d_w1l[256*128];   // w1 hi/lo fp16
__device__ int   d_idx[COLS];
__device__ float d_out0[(size_t)COLS*128];          // pre-BN layer-0 acts, [j][k]
__device__ float d_pmax[(size_t)PTOT*256];          // [q][c]
__device__ float d_pmin[(size_t)PTOT*256];
__device__ float d_stats[768];
__device__ float d_sc0[64], d_bi0[64], d_sc1[3], d_bi1[3];
__device__ float d_scm0[128], d_bim0[128], d_scm1[256], d_bim1[256];

// ---------------- helpers ----------------
__device__ __forceinline__ uint32_t smem_u32(const void* p){
    uint32_t a;
    asm("{ .reg .u64 t; cvta.to.shared.u64 t, %1; cvt.u32.u64 %0, t; }" : "=r"(a) : "l"(p));
    return a;
}
__device__ __forceinline__ void hsplit(float x, __half& h, __half& l){
    h = __float2half_rn(x);
    l = __float2half_rn(x - __half2float(h));
}
__device__ __forceinline__ void mma_f16(float& c0, float& c1, float& c2, float& c3,
                                        unsigned a0, unsigned a1, unsigned a2, unsigned a3,
                                        unsigned b0, unsigned b1){
    asm volatile("mma.sync.aligned.m16n8k16.row.col.f32.f16.f16.f32 "
        "{%0,%1,%2,%3}, {%4,%5,%6,%7}, {%8,%9}, {%0,%1,%2,%3};"
        : "+f"(c0), "+f"(c1), "+f"(c2), "+f"(c3)
        : "r"(a0), "r"(a1), "r"(a2), "r"(a3), "r"(b0), "r"(b1));
}
__device__ __forceinline__ void ldsm4(unsigned& r0, unsigned& r1, unsigned& r2, unsigned& r3, uint32_t a){
    asm volatile("ldmatrix.sync.aligned.m8n8.x4.shared.b16 {%0,%1,%2,%3}, [%4];"
        : "=r"(r0), "=r"(r1), "=r"(r2), "=r"(r3) : "r"(a));
}
__device__ __forceinline__ void ldsm2(unsigned& r0, unsigned& r1, uint32_t a){
    asm volatile("ldmatrix.sync.aligned.m8n8.x2.shared.b16 {%0,%1}, [%2];"
        : "=r"(r0), "=r"(r1) : "r"(a));
}
__device__ __forceinline__ void cpa16(uint32_t dst, const void* src){
    asm volatile("cp.async.cg.shared.global [%0], [%1], 16;" :: "r"(dst), "l"(src));
}
__device__ __forceinline__ void cpwait(){
    asm volatile("cp.async.commit_group;\n\tcp.async.wait_group 0;" ::: "memory");
}
__device__ __forceinline__ float red4sum(float v){
    v += __shfl_xor_sync(0xffffffffu, v, 1, 4);
    v += __shfl_xor_sync(0xffffffffu, v, 2, 4);
    return v;
}
__device__ __forceinline__ float red4max(float v){
    v = fmaxf(v, __shfl_xor_sync(0xffffffffu, v, 1, 4));
    v = fmaxf(v, __shfl_xor_sync(0xffffffffu, v, 2, 4));
    return v;
}
__device__ __forceinline__ float red4min(float v){
    v = fminf(v, __shfl_xor_sync(0xffffffffu, v, 1, 4));
    v = fminf(v, __shfl_xor_sync(0xffffffffu, v, 2, 4));
    return v;
}
__device__ __forceinline__ uint4 packh8(const float* f){
    unsigned p[4];
    #pragma unroll
    for (int i = 0; i < 4; i++){
        __half h0 = __float2half_rn(f[2*i]);
        __half h1 = __float2half_rn(f[2*i+1]);
        p[i] = ((unsigned)__half_as_ushort(h1) << 16) | __half_as_ushort(h0);
    }
    return make_uint4(p[0], p[1], p[2], p[3]);
}

// ---------------- small kernels ----------------
__global__ void kzero(){
    int i = blockIdx.x*blockDim.x + threadIdx.x;
    if (i < 768) d_stats[i] = 0.f;
}

__global__ void kwprep(const float* __restrict__ w0, const float* __restrict__ w1){
    int i = blockIdx.x*256 + threadIdx.x;
    if (i < 128*128){
        int r = i >> 7, k = i & 127;
        __half h, l; hsplit(w0[r*131 + 3 + k], h, l);
        d_w0h[i] = h; d_w0l[i] = l;
    } else if (i < 128*128 + 256*128){
        int j = i - 128*128;
        __half h, l; hsplit(w1[j], h, l);
        d_w1h[j] = h; d_w1l[j] = l;
    }
}

__global__ void ks1(const float* __restrict__ ffps, const float* __restrict__ w0){
    int p = blockIdx.x*blockDim.x + threadIdx.x;
    float f0 = ffps[p*3+0], f1 = ffps[p*3+1], f2 = ffps[p*3+2];
    #pragma unroll 4
    for (int c = 0; c < 64; c++){
        float v = w0[c*3+0]*f0 + w0[c*3+1]*f1 + w0[c*3+2]*f2;
        d_h0[c*PTOT + p] = v;
    }
}

__global__ void kstat(int which, const float* __restrict__ g, const float* __restrict__ bb){
    __shared__ float ss[256], sq[256];
    int c = blockIdx.x;
    const float* buf = (which == 0 ? d_h0 : d_h1) + c*PTOT;
    float s = 0.f, q = 0.f;
    for (int i = threadIdx.x; i < PTOT; i += 256){
        float v = buf[i]; s += v; q = fmaf(v, v, q);
    }
    ss[threadIdx.x] = s; sq[threadIdx.x] = q; __syncthreads();
    for (int o = 128; o > 0; o >>= 1){
        if (threadIdx.x < o){
            ss[threadIdx.x] += ss[threadIdx.x+o];
            sq[threadIdx.x] += sq[threadIdx.x+o];
        }
        __syncthreads();
    }
    if (threadIdx.x == 0){
        float mean = ss[0] / (float)PTOT;
        float var  = sq[0] / (float)PTOT - mean*mean;
        float scl  = g[c] * rsqrtf(var + EPSV);
        if (which == 0){ d_sc0[c] = scl; d_bi0[c] = fmaf(-mean, scl, bb[c]); }
        else           { d_sc1[c] = scl; d_bi1[c] = fmaf(-mean, scl, bb[c]); }
    }
}

// shift layer 1: 4 threads per point, 16 channels each, shuffle reduce
__global__ void ks2(const float* __restrict__ w1){
    int idx = blockIdx.x*blockDim.x + threadIdx.x;
    int p = idx >> 2, q = idx & 3;
    float a0 = 0.f, a1 = 0.f, a2 = 0.f;
    #pragma unroll 4
    for (int c = q; c < 64; c += 4){
        float v = fmaxf(fmaf(d_sc0[c], d_h0[c*PTOT + p], d_bi0[c]), 0.f);
        a0 = fmaf(w1[c],       v, a0);
        a1 = fmaf(w1[64 + c],  v, a1);
        a2 = fmaf(w1[128 + c], v, a2);
    }
    a0 = red4sum(a0); a1 = red4sum(a1); a2 = red4sum(a2);
    if (q == 0){
        d_h1[p] = a0; d_h1[PTOT + p] = a1; d_h1[2*PTOT + p] = a2;
    }
}

__global__ void ks3(){
    int p = blockIdx.x*blockDim.x + threadIdx.x;
    #pragma unroll
    for (int o = 0; o < 3; o++)
        d_nxyz[p*3 + o] = fmaxf(fmaf(d_sc1[o], d_h1[o*PTOT + p], d_bi1[o]), 0.f);
}

// transpose features (B,C,N) -> [b][n][c] fp16
__global__ void ktr(const float* __restrict__ feat){
    __shared__ float t[32][33];
    int b = blockIdx.z, n0 = blockIdx.x*32, c0 = blockIdx.y*32;
    for (int i = threadIdx.y; i < 32; i += 8)
        t[i][threadIdx.x] = feat[((size_t)b*CF + (c0+i))*NPT + n0 + threadIdx.x];
    __syncthreads();
    for (int i = threadIdx.y; i < 32; i += 8){
        size_t o = ((size_t)b*NPT + (n0+i))*CF + c0 + threadIdx.x;
        d_fh[o] = __float2half_rn(t[threadIdx.x][i]);
    }
}

__global__ void kballq(const float* __restrict__ bxyz){
    int gw = (blockIdx.x*blockDim.x + threadIdx.x) >> 5;
    int lane = threadIdx.x & 31;
    int b = gw >> 11;
    float q0 = d_nxyz[gw*3+0], q1 = d_nxyz[gw*3+1], q2 = d_nxyz[gw*3+2];
    float qq = q0*q0 + q1*q1 + q2*q2;
    const float* xb = bxyz + (size_t)b*NPT*3;
    int cnt = 0, firstIdx = -1;
    for (int base = 0; base < NPT; base += 32){
        int n = base + lane;
        float x0 = xb[n*3+0], x1 = xb[n*3+1], x2 = xb[n*3+2];
        float xx = x0*x0 + x1*x1 + x2*x2;
        float dot = q0*x0 + q1*x1 + q2*x2;
        float d2 = (qq + xx) - 2.0f*dot;
        bool hit = d2 < R2;
        unsigned bal = __ballot_sync(0xffffffffu, hit);
        if (firstIdx < 0 && bal) firstIdx = base + __ffs(bal) - 1;
        if (hit){
            int pos = cnt + __popc(bal & ((1u << lane) - 1u));
            if (pos < NS) d_idx[gw*NS + pos] = n;
        }
        cnt += __popc(bal);
        if (cnt >= NS) break;
    }
    if (cnt < NS){
        int f = (firstIdx < 0) ? 0 : firstIdx;
        if (lane >= cnt) d_idx[gw*NS + lane] = f;
    }
}

// ---------------- GEMM kernels (fp16 2-term HMMA, occ=2) ----------------
// padded fp16 tiles: row = 256B payload, stride 272B — conflict-free ldmatrix
#define TSB  272
// kg1 smem: Ah(34816) Al(34816) Bh(34816) rel(1536)
#define K1_AH 0
#define K1_AL 34816
#define K1_BH 69632
#define K1_REL 104448
#define K1_SMEM (104448 + 1536)
// kg2 smem: Ah(34816) Al(34816) Bh(34816) sc(1024)
#define K2_AH 0
#define K2_AL 34816
#define K2_BH 69632
#define K2_SC 104448
#define K2_SMEM (104448 + 1024)

// GEMM1: 128x128 tile of out0 = W0feat @ gathered feats; rel via FFMA epilogue.
__global__ void __launch_bounds__(256, 2) kg1(const float* __restrict__ w0,
                                              const float* __restrict__ bxyz){
    extern __shared__ char smx[];
    float* relS = (float*)(smx + K1_REL);
    const int tid = threadIdx.x;
    const int lane = tid & 31, wid = tid >> 5;
    const int g = lane >> 2, tid4 = lane & 3;
    const int m0 = (wid & 3) * 32;          // 2 m16 tiles
    const int wn = wid >> 2;
    const int n0 = wn * 64;                 // 8 n8 tiles
    const int jb = blockIdx.x * 128;
    uint32_t sb = smem_u32(smx);

    // A fill: pre-split w0 hi/lo via cp.async
    for (int e = tid; e < 2048; e += 256){
        int r = e >> 4, kc = e & 15;
        uint32_t d = sb + K1_AH + r*TSB + kc*16;
        cpa16(d, d_w0h + r*128 + kc*8);
        cpa16(d + (K1_AL - K1_AH), d_w0l + r*128 + kc*8);
    }
    // B gather (fp16 hi only) + rel
    {
        int col = tid >> 1, half = tid & 1;
        int j = jb + col;
        int b = j >> 16;
        int m = (j & 65535) >> 5;
        int n = d_idx[j];
        size_t base = ((size_t)(b*NPT + n))*CF + half*64;
        uint32_t db = sb + K1_BH + col*TSB + half*128;
        #pragma unroll
        for (int i = 0; i < 8; i++)
            cpa16(db + i*16, d_fh + base + i*8);
        if (half == 0){
            const float* xp = bxyz + (size_t)(b*NPT + n)*3;
            const float* qp = d_nxyz + (size_t)(b*MQ + m)*3;
            relS[col]       = xp[0] - qp[0];
            relS[128 + col] = xp[1] - qp[1];
            relS[256 + col] = xp[2] - qp[2];
        }
    }
    cpwait();
    __syncthreads();

    uint32_t aH[2], aL[2], bHa[8];
    #pragma unroll
    for (int mt = 0; mt < 2; mt++){
        int row = m0 + mt*16 + (lane & 15);
        uint32_t off = row*TSB + ((lane & 16) ? 16 : 0);
        aH[mt] = sb + K1_AH + off;
        aL[mt] = sb + K1_AL + off;
    }
    #pragma unroll
    for (int nt = 0; nt < 8; nt++){
        int row = n0 + nt*8 + (lane & 7);
        uint32_t off = row*TSB + (((lane >> 3) & 1) << 4);
        bHa[nt] = sb + K1_BH + off;
    }

    float acc[2][8][4];
    #pragma unroll
    for (int mt = 0; mt < 2; mt++)
        #pragma unroll
        for (int nt = 0; nt < 8; nt++)
            #pragma unroll
            for (int c = 0; c < 4; c++) acc[mt][nt][c] = 0.f;

    #pragma unroll
    for (int ks = 0; ks < 8; ks++){
        const uint32_t kd = ks*32;
        unsigned ah[2][4], al[2][4];
        #pragma unroll
        for (int mt = 0; mt < 2; mt++){
            ldsm4(ah[mt][0], ah[mt][1], ah[mt][2], ah[mt][3], aH[mt] + kd);
            ldsm4(al[mt][0], al[mt][1], al[mt][2], al[mt][3], aL[mt] + kd);
        }
        #pragma unroll
        for (int nt = 0; nt < 8; nt++){
            unsigned b0, b1;
            ldsm2(b0, b1, bHa[nt] + kd);
            #pragma unroll
            for (int mt = 0; mt < 2; mt++){
                float* a = acc[mt][nt];
                mma_f16(a[0],a[1],a[2],a[3], ah[mt][0],ah[mt][1],ah[mt][2],ah[mt][3], b0,b1);
                mma_f16(a[0],a[1],a[2],a[3], al[mt][0],al[mt][1],al[mt][2],al[mt][3], b0,b1);
            }
        }
    }
    __syncthreads();

    float* red = (float*)smx;           // 256 floats (reuses A region)
    red[tid] = 0.f;
    __syncthreads();

    float wr[2][2][3];
    #pragma unroll
    for (int mt = 0; mt < 2; mt++)
        #pragma unroll
        for (int rh = 0; rh < 2; rh++){
            int r = m0 + mt*16 + g + rh*8;
            wr[mt][rh][0] = __ldg(&w0[r*131+0]);
            wr[mt][rh][1] = __ldg(&w0[r*131+1]);
            wr[mt][rh][2] = __ldg(&w0[r*131+2]);
        }
    float rs[2][2] = {{0,0},{0,0}}, rq[2][2] = {{0,0},{0,0}};
    #pragma unroll
    for (int nt = 0; nt < 8; nt++){
        int c = n0 + nt*8 + tid4*2;
        float r00 = relS[c],     r01 = relS[c+1];
        float r10 = relS[128+c], r11 = relS[129+c];
        float r20 = relS[256+c], r21 = relS[257+c];
        #pragma unroll
        for (int mt = 0; mt < 2; mt++){
            float* a = acc[mt][nt];
            a[0] += wr[mt][0][0]*r00 + wr[mt][0][1]*r10 + wr[mt][0][2]*r20;
            a[1] += wr[mt][0][0]*r01 + wr[mt][0][1]*r11 + wr[mt][0][2]*r21;
            a[2] += wr[mt][1][0]*r00 + wr[mt][1][1]*r10 + wr[mt][1][2]*r20;
            a[3] += wr[mt][1][0]*r01 + wr[mt][1][1]*r11 + wr[mt][1][2]*r21;
            int r0 = m0 + mt*16 + g, r1 = r0 + 8;
            size_t cb = (size_t)(jb + c) * 128;
            d_out0[cb + r0]       = a[0];
            d_out0[cb + 128 + r0] = a[1];
            d_out0[cb + r1]       = a[2];
            d_out0[cb + 128 + r1] = a[3];
            rs[mt][0] += a[0] + a[1]; rq[mt][0] += a[0]*a[0] + a[1]*a[1];
            rs[mt][1] += a[2] + a[3]; rq[mt][1] += a[2]*a[2] + a[3]*a[3];
        }
    }
    #pragma unroll
    for (int mt = 0; mt < 2; mt++)
        #pragma unroll
        for (int rh = 0; rh < 2; rh++){
            float s = red4sum(rs[mt][rh]);
            float q = red4sum(rq[mt][rh]);
            if (tid4 == 0){
                int r = m0 + mt*16 + g + rh*8;
                atomicAdd(&red[r], s);
                atomicAdd(&red[128 + r], q);
            }
        }
    __syncthreads();
    if (tid < 128){
        atomicAdd(&d_stats[tid],       red[tid]);
        atomicAdd(&d_stats[128 + tid], red[128 + tid]);
    }
}

__global__ void kfm(int which, const float* __restrict__ g, const float* __restrict__ bb){
    int c = threadIdx.x;
    float inv = 1.0f / (float)COLS;
    int so = (which == 0) ? 0 : 256;
    int qo = (which == 0) ? 128 : 512;
    float mean = d_stats[so + c] * inv;
    float var  = d_stats[qo + c] * inv - mean*mean;
    float scl  = g[c] * rsqrtf(var + EPSV);
    if (which == 0){ d_scm0[c] = scl; d_bim0[c] = fmaf(-mean, scl, bb[c]); }
    else           { d_scm1[c] = scl; d_bim1[c] = fmaf(-mean, scl, bb[c]); }
}

// GEMM2: grid (2048, 2): y = row half; fused BN+relu on load, stats + max/min pool.
__global__ void __launch_bounds__(256, 2) kg2(){
    extern __shared__ char smx[];
    float* scS = (float*)(smx + K2_SC);     // [0:128) scale, [128:256) bias
    const int tid = threadIdx.x;
    const int lane = tid & 31, wid = tid >> 5;
    const int g = lane >> 2, tid4 = lane & 3;
    const int m0 = (wid & 3) * 32;          // 2 m16 tiles of 128 local rows
    const int wn = wid >> 2;
    const int n0 = wn * 64;                 // 8 n8 tiles
    const int jb = blockIdx.x * 128;
    const int rowOff = blockIdx.y * 128;
    uint32_t sb = smem_u32(smx);

    if (tid < 128){ scS[tid] = d_scm0[tid]; scS[128 + tid] = d_bim0[tid]; }

    // A fill: pre-split w1 rows [rowOff, rowOff+128)
    for (int e = tid; e < 2048; e += 256){
        int r = e >> 4, kc = e & 15;
        uint32_t d = sb + K2_AH + r*TSB + kc*16;
        cpa16(d, d_w1h + (rowOff + r)*128 + kc*8);
        cpa16(d + (K2_AL - K2_AH), d_w1l + (rowOff + r)*128 + kc*8);
    }
    __syncthreads();                        // scS visible

    // B fill: load out0 col, BN+relu, fp16 pack, STS.128
    {
        int col = tid >> 1, half = tid & 1;
        const float* src = d_out0 + (size_t)(jb + col)*128 + half*64;
        char* bh = smx + K2_BH + col*TSB + half*128;
        #pragma unroll
        for (int kc = 0; kc < 8; kc++){
            float4 x0 = *(const float4*)(src + kc*8);
            float4 x1 = *(const float4*)(src + kc*8 + 4);
            float f[8] = {x0.x, x0.y, x0.z, x0.w, x1.x, x1.y, x1.z, x1.w};
            #pragma unroll
            for (int i = 0; i < 8; i++){
                int k = half*64 + kc*8 + i;
                f[i] = fmaxf(fmaf(scS[k], f[i], scS[128 + k]), 0.f);
            }
            *(uint4*)(bh + kc*16) = packh8(f);
        }
    }
    cpwait();
    __syncthreads();

    uint32_t aH[2], aL[2], bHa[8];
    #pragma unroll
    for (int mt = 0; mt < 2; mt++){
        int row = m0 + mt*16 + (lane & 15);
        uint32_t off = row*TSB + ((lane & 16) ? 16 : 0);
        aH[mt] = sb + K2_AH + off;
        aL[mt] = sb + K2_AL + off;
    }
    #pragma unroll
    for (int nt = 0; nt < 8; nt++){
        int row = n0 + nt*8 + (lane & 7);
        uint32_t off = row*TSB + (((lane >> 3) & 1) << 4);
        bHa[nt] = sb + K2_BH + off;
    }

    float acc[2][8][4];
    #pragma unroll
    for (int mt = 0; mt < 2; mt++)
        #pragma unroll
        for (int nt = 0; nt < 8; nt++)
            #pragma unroll
            for (int c = 0; c < 4; c++) acc[mt][nt][c] = 0.f;

    #pragma unroll
    for (int ks = 0; ks < 8; ks++){
        const uint32_t kd = ks*32;
        unsigned ah[2][4], al[2][4];
        #pragma unroll
        for (int mt = 0; mt < 2; mt++){
            ldsm4(ah[mt][0], ah[mt][1], ah[mt][2], ah[mt][3], aH[mt] + kd);
            ldsm4(al[mt][0], al[mt][1], al[mt][2], al[mt][3], aL[mt] + kd);
        }
        #pragma unroll
        for (int nt = 0; nt < 8; nt++){
            unsigned b0, b1;
            ldsm2(b0, b1, bHa[nt] + kd);
            #pragma unroll
            for (int mt = 0; mt < 2; mt++){
                float* a = acc[mt][nt];
                mma_f16(a[0],a[1],a[2],a[3], ah[mt][0],ah[mt][1],ah[mt][2],ah[mt][3], b0,b1);
                mma_f16(a[0],a[1],a[2],a[3], al[mt][0],al[mt][1],al[mt][2],al[mt][3], b0,b1);
            }
        }
    }
    __syncthreads();

    float* red = (float*)smx;               // 256 floats
    red[tid] = 0.f;
    __syncthreads();

    float rs[2][2] = {{0,0},{0,0}}, rq[2][2] = {{0,0},{0,0}};
    float mx[2][2][2], mn[2][2][2];
    #pragma unroll
    for (int mt = 0; mt < 2; mt++)
        #pragma unroll
        for (int rh = 0; rh < 2; rh++)
            #pragma unroll
            for (int qi = 0; qi < 2; qi++){ mx[mt][rh][qi] = -3.4e38f; mn[mt][rh][qi] = 3.4e38f; }

    #pragma unroll
    for (int nt = 0; nt < 8; nt++){
        int qi = nt >> 2;
        #pragma unroll
        for (int mt = 0; mt < 2; mt++){
            float* a = acc[mt][nt];
            rs[mt][0] += a[0] + a[1]; rq[mt][0] += a[0]*a[0] + a[1]*a[1];
            rs[mt][1] += a[2] + a[3]; rq[mt][1] += a[2]*a[2] + a[3]*a[3];
            mx[mt][0][qi] = fmaxf(mx[mt][0][qi], fmaxf(a[0], a[1]));
            mn[mt][0][qi] = fminf(mn[mt][0][qi], fminf(a[0], a[1]));
            mx[mt][1][qi] = fmaxf(mx[mt][1][qi], fmaxf(a[2], a[3]));
            mn[mt][1][qi] = fminf(mn[mt][1][qi], fminf(a[2], a[3]));
        }
    }
    #pragma unroll
    for (int mt = 0; mt < 2; mt++)
        #pragma unroll
        for (int rh = 0; rh < 2; rh++){
            float s = red4sum(rs[mt][rh]);
            float q = red4sum(rq[mt][rh]);
            int rl = m0 + mt*16 + g + rh*8;
            int rg = rowOff + rl;
            #pragma unroll
            for (int qi = 0; qi < 2; qi++){
                float vmx = red4max(mx[mt][rh][qi]);
                float vmn = red4min(mn[mt][rh][qi]);
                if (tid4 == 0){
                    int qg = blockIdx.x*4 + wn*2 + qi;
                    d_pmax[(size_t)qg*256 + rg] = vmx;
                    d_pmin[(size_t)qg*256 + rg] = vmn;
                }
            }
            if (tid4 == 0){
                atomicAdd(&red[rl], s);
                atomicAdd(&red[128 + rl], q);
            }
        }
    __syncthreads();
    if (tid < 128){
        atomicAdd(&d_stats[256 + rowOff + tid], red[tid]);
        atomicAdd(&d_stats[512 + rowOff + tid], red[128 + tid]);
    }
}

// final: out[p][c] = relu(s*pooled + t), pooled = max if s>=0 else min
__global__ void kfin(float* __restrict__ out){
    int c = threadIdx.x;
    int p = blockIdx.x;
    float s = d_scm1[c], t = d_bim1[c];
    float v = (s >= 0.f) ? d_pmax[(size_t)p*256 + c] : d_pmin[(size_t)p*256 + c];
    out[(size_t)p*256 + c] = fmaxf(fmaf(s, v, t), 0.f);
}

// ---------------- launch ----------------
extern "C" void kernel_launch(void* const* d_in, const int* in_sizes, int n_in,
                              void* d_out, int out_size){
    (void)in_sizes; (void)n_in; (void)out_size;
    const float* ffps = (const float*)d_in[0];
    const float* bxyz = (const float*)d_in[1];
    const float* bfeat= (const float*)d_in[2];
    const float* sw0  = (const float*)d_in[3];
    const float* sg0  = (const float*)d_in[4];
    const float* sb0  = (const float*)d_in[5];
    const float* sw1  = (const float*)d_in[6];
    const float* sg1  = (const float*)d_in[7];
    const float* sb1  = (const float*)d_in[8];
    const float* mw0  = (const float*)d_in[9];
    const float* mg0  = (const float*)d_in[10];
    const float* mb0  = (const float*)d_in[11];
    const float* mw1  = (const float*)d_in[12];
    const float* mg1  = (const float*)d_in[13];
    const float* mb1  = (const float*)d_in[14];
    float* out = (float*)d_out;

    cudaFuncSetAttribute(kg1, cudaFuncAttributeMaxDynamicSharedMemorySize, K1_SMEM);
    cudaFuncSetAttribute(kg2, cudaFuncAttributeMaxDynamicSharedMemorySize, K2_SMEM);

    kzero<<<3, 256>>>();
    kwprep<<<(128*128 + 256*128 + 255)/256, 256>>>(mw0, mw1);
    ks1<<<PTOT/256, 256>>>(ffps, sw0);
    kstat<<<64, 256>>>(0, sg0, sb0);
    ks2<<<PTOT*4/256, 256>>>(sw1);
    kstat<<<3, 256>>>(1, sg1, sb1);
    ks3<<<PTOT/256, 256>>>();
    ktr<<<dim3(NPT/32, CF/32, BQ), dim3(32, 8)>>>(bfeat);
    kballq<<<PTOT/8, 256>>>(bxyz);
    kg1<<<COLS/128, 256, K1_SMEM>>>(mw0, bxyz);
    kfm<<<1, 128>>>(0, mg0, mb0);
    kg2<<<dim3(COLS/128, 2), 256, K2_SMEM>>>();
    kfm<<<1, 256>>>(1, mg1, mb1);
    kfin<<<PTOT, 256>>>(out);
}

// round 16
// speedup vs baseline: 5.4630x; 1.2106x over previous
#include <cuda_runtime.h>
#include <cuda_fp16.h>
#include <cstdint>

#define BQ   4
#define NPT  16384
#define MQ   2048
#define CF   128
#define NS   32
#define PTOT (BQ*MQ)        // 8192 query points
#define COLS (PTOT*NS)      // 262144 GEMM columns
#define R2   9.0f
#define EPSV 1e-5f

// ---------------- static scratch (allocation-free rule) ----------------
__device__ float d_h0[64*PTOT];
__device__ float d_h1[3*PTOT];
__device__ float d_nxyz[PTOT*3];
__device__ __half d_fh[(size_t)BQ*NPT*CF];          // features fp16 [b][n][c]
__device__ __half d_w0h[128*128], d_w0l[128*128];   // w0 feature part hi/lo fp16
__device__ __half d_w1h[256*128], d_w1l[256*128];   // w1 hi/lo fp16
__device__ int   d_idx[COLS];
__device__ __half d_out0h[(size_t)COLS*128];        // pre-BN layer-0 acts, [j][k] fp16
__device__ float d_pmax[(size_t)PTOT*256];          // [q][c]
__device__ float d_pmin[(size_t)PTOT*256];
__device__ float d_stats[768];
__device__ float d_sc0[64], d_bi0[64], d_sc1[3], d_bi1[3];
__device__ float d_scm0[128], d_bim0[128], d_scm1[256], d_bim1[256];

// ---------------- helpers ----------------
__device__ __forceinline__ uint32_t smem_u32(const void* p){
    uint32_t a;
    asm("{ .reg .u64 t; cvta.to.shared.u64 t, %1; cvt.u32.u64 %0, t; }" : "=r"(a) : "l"(p));
    return a;
}
__device__ __forceinline__ void hsplit(float x, __half& h, __half& l){
    h = __float2half_rn(x);
    l = __float2half_rn(x - __half2float(h));
}
__device__ __forceinline__ void mma_f16(float& c0, float& c1, float& c2, float& c3,
                                        unsigned a0, unsigned a1, unsigned a2, unsigned a3,
                                        unsigned b0, unsigned b1){
    asm volatile("mma.sync.aligned.m16n8k16.row.col.f32.f16.f16.f32 "
        "{%0,%1,%2,%3}, {%4,%5,%6,%7}, {%8,%9}, {%0,%1,%2,%3};"
        : "+f"(c0), "+f"(c1), "+f"(c2), "+f"(c3)
        : "r"(a0), "r"(a1), "r"(a2), "r"(a3), "r"(b0), "r"(b1));
}
__device__ __forceinline__ void ldsm4(unsigned& r0, unsigned& r1, unsigned& r2, unsigned& r3, uint32_t a){
    asm volatile("ldmatrix.sync.aligned.m8n8.x4.shared.b16 {%0,%1,%2,%3}, [%4];"
        : "=r"(r0), "=r"(r1), "=r"(r2), "=r"(r3) : "r"(a));
}
__device__ __forceinline__ void cpa16(uint32_t dst, const void* src){
    asm volatile("cp.async.cg.shared.global [%0], [%1], 16;" :: "r"(dst), "l"(src));
}
__device__ __forceinline__ void cpwait(){
    asm volatile("cp.async.commit_group;\n\tcp.async.wait_group 0;" ::: "memory");
}
__device__ __forceinline__ float red4sum(float v){
    v += __shfl_xor_sync(0xffffffffu, v, 1, 4);
    v += __shfl_xor_sync(0xffffffffu, v, 2, 4);
    return v;
}
__device__ __forceinline__ float red4max(float v){
    v = fmaxf(v, __shfl_xor_sync(0xffffffffu, v, 1, 4));
    v = fmaxf(v, __shfl_xor_sync(0xffffffffu, v, 2, 4));
    return v;
}
__device__ __forceinline__ float red4min(float v){
    v = fminf(v, __shfl_xor_sync(0xffffffffu, v, 1, 4));
    v = fminf(v, __shfl_xor_sync(0xffffffffu, v, 2, 4));
    return v;
}

// ---------------- small kernels ----------------
__global__ void kzero(){
    int i = blockIdx.x*blockDim.x + threadIdx.x;
    if (i < 768) d_stats[i] = 0.f;
}

__global__ void kwprep(const float* __restrict__ w0, const float* __restrict__ w1){
    int i = blockIdx.x*256 + threadIdx.x;
    if (i < 128*128){
        int r = i >> 7, k = i & 127;
        __half h, l; hsplit(w0[r*131 + 3 + k], h, l);
        d_w0h[i] = h; d_w0l[i] = l;
    } else if (i < 128*128 + 256*128){
        int j = i - 128*128;
        __half h, l; hsplit(w1[j], h, l);
        d_w1h[j] = h; d_w1l[j] = l;
    }
}

__global__ void ks1(const float* __restrict__ ffps, const float* __restrict__ w0){
    int p = blockIdx.x*blockDim.x + threadIdx.x;
    float f0 = ffps[p*3+0], f1 = ffps[p*3+1], f2 = ffps[p*3+2];
    #pragma unroll 4
    for (int c = 0; c < 64; c++){
        float v = w0[c*3+0]*f0 + w0[c*3+1]*f1 + w0[c*3+2]*f2;
        d_h0[c*PTOT + p] = v;
    }
}

__global__ void kstat(int which, const float* __restrict__ g, const float* __restrict__ bb){
    __shared__ float ss[256], sq[256];
    int c = blockIdx.x;
    const float* buf = (which == 0 ? d_h0 : d_h1) + c*PTOT;
    float s = 0.f, q = 0.f;
    for (int i = threadIdx.x; i < PTOT; i += 256){
        float v = buf[i]; s += v; q = fmaf(v, v, q);
    }
    ss[threadIdx.x] = s; sq[threadIdx.x] = q; __syncthreads();
    for (int o = 128; o > 0; o >>= 1){
        if (threadIdx.x < o){
            ss[threadIdx.x] += ss[threadIdx.x+o];
            sq[threadIdx.x] += sq[threadIdx.x+o];
        }
        __syncthreads();
    }
    if (threadIdx.x == 0){
        float mean = ss[0] / (float)PTOT;
        float var  = sq[0] / (float)PTOT - mean*mean;
        float scl  = g[c] * rsqrtf(var + EPSV);
        if (which == 0){ d_sc0[c] = scl; d_bi0[c] = fmaf(-mean, scl, bb[c]); }
        else           { d_sc1[c] = scl; d_bi1[c] = fmaf(-mean, scl, bb[c]); }
    }
}

// shift layer 1: 4 threads per point, 16 channels each, shuffle reduce
__global__ void ks2(const float* __restrict__ w1){
    int idx = blockIdx.x*blockDim.x + threadIdx.x;
    int p = idx >> 2, q = idx & 3;
    float a0 = 0.f, a1 = 0.f, a2 = 0.f;
    #pragma unroll 4
    for (int c = q; c < 64; c += 4){
        float v = fmaxf(fmaf(d_sc0[c], d_h0[c*PTOT + p], d_bi0[c]), 0.f);
        a0 = fmaf(w1[c],       v, a0);
        a1 = fmaf(w1[64 + c],  v, a1);
        a2 = fmaf(w1[128 + c], v, a2);
    }
    a0 = red4sum(a0); a1 = red4sum(a1); a2 = red4sum(a2);
    if (q == 0){
        d_h1[p] = a0; d_h1[PTOT + p] = a1; d_h1[2*PTOT + p] = a2;
    }
}

__global__ void ks3(){
    int p = blockIdx.x*blockDim.x + threadIdx.x;
    #pragma unroll
    for (int o = 0; o < 3; o++)
        d_nxyz[p*3 + o] = fmaxf(fmaf(d_sc1[o], d_h1[o*PTOT + p], d_bi1[o]), 0.f);
}

// transpose features (B,C,N) -> [b][n][c] fp16
__global__ void ktr(const float* __restrict__ feat){
    __shared__ float t[32][33];
    int b = blockIdx.z, n0 = blockIdx.x*32, c0 = blockIdx.y*32;
    for (int i = threadIdx.y; i < 32; i += 8)
        t[i][threadIdx.x] = feat[((size_t)b*CF + (c0+i))*NPT + n0 + threadIdx.x];
    __syncthreads();
    for (int i = threadIdx.y; i < 32; i += 8){
        size_t o = ((size_t)b*NPT + (n0+i))*CF + c0 + threadIdx.x;
        d_fh[o] = __float2half_rn(t[threadIdx.x][i]);
    }
}

__global__ void kballq(const float* __restrict__ bxyz){
    int gw = (blockIdx.x*blockDim.x + threadIdx.x) >> 5;
    int lane = threadIdx.x & 31;
    int b = gw >> 11;
    float q0 = d_nxyz[gw*3+0], q1 = d_nxyz[gw*3+1], q2 = d_nxyz[gw*3+2];
    float qq = q0*q0 + q1*q1 + q2*q2;
    const float* xb = bxyz + (size_t)b*NPT*3;
    int cnt = 0, firstIdx = -1;
    for (int base = 0; base < NPT; base += 32){
        int n = base + lane;
        float x0 = xb[n*3+0], x1 = xb[n*3+1], x2 = xb[n*3+2];
        float xx = x0*x0 + x1*x1 + x2*x2;
        float dot = q0*x0 + q1*x1 + q2*x2;
        float d2 = (qq + xx) - 2.0f*dot;
        bool hit = d2 < R2;
        unsigned bal = __ballot_sync(0xffffffffu, hit);
        if (firstIdx < 0 && bal) firstIdx = base + __ffs(bal) - 1;
        if (hit){
            int pos = cnt + __popc(bal & ((1u << lane) - 1u));
            if (pos < NS) d_idx[gw*NS + pos] = n;
        }
        cnt += __popc(bal);
        if (cnt >= NS) break;
    }
    if (cnt < NS){
        int f = (firstIdx < 0) ? 0 : firstIdx;
        if (lane >= cnt) d_idx[gw*NS + lane] = f;
    }
}

// ---------------- GEMM kernels (fp16 2-term HMMA, occ=2, ldsm-x4 B) ----------------
#define TSB  272
#define K1_AH 0
#define K1_AL 34816
#define K1_BH 69632
#define K1_REL 104448
#define K1_SMEM (104448 + 1536)
#define K2_AH 0
#define K2_AL 34816
#define K2_BH 69632
#define K2_SC 104448
#define K2_SMEM (104448 + 1024)

// GEMM1: 128x128 tile of out0 = W0feat @ gathered feats; rel via FFMA epilogue.
__global__ void __launch_bounds__(256, 2) kg1(const float* __restrict__ w0,
                                              const float* __restrict__ bxyz){
    extern __shared__ char smx[];
    float* relS = (float*)(smx + K1_REL);
    const int tid = threadIdx.x;
    const int lane = tid & 31, wid = tid >> 5;
    const int g = lane >> 2, tid4 = lane & 3;
    const int m0 = (wid & 3) * 32;          // 2 m16 tiles
    const int wn = wid >> 2;
    const int n0 = wn * 64;                 // 8 n8 tiles (4 pairs)
    const int jb = blockIdx.x * 128;
    uint32_t sb = smem_u32(smx);

    // A fill: pre-split w0 hi/lo via cp.async
    for (int e = tid; e < 2048; e += 256){
        int r = e >> 4, kc = e & 15;
        uint32_t d = sb + K1_AH + r*TSB + kc*16;
        cpa16(d, d_w0h + r*128 + kc*8);
        cpa16(d + (K1_AL - K1_AH), d_w0l + r*128 + kc*8);
    }
    // B gather (fp16) + rel
    {
        int col = tid >> 1, half = tid & 1;
        int j = jb + col;
        int b = j >> 16;
        int m = (j & 65535) >> 5;
        int n = d_idx[j];
        size_t base = ((size_t)(b*NPT + n))*CF + half*64;
        uint32_t db = sb + K1_BH + col*TSB + half*128;
        #pragma unroll
        for (int i = 0; i < 8; i++)
            cpa16(db + i*16, d_fh + base + i*8);
        if (half == 0){
            const float* xp = bxyz + (size_t)(b*NPT + n)*3;
            const float* qp = d_nxyz + (size_t)(b*MQ + m)*3;
            relS[col]       = xp[0] - qp[0];
            relS[128 + col] = xp[1] - qp[1];
            relS[256 + col] = xp[2] - qp[2];
        }
    }
    cpwait();
    __syncthreads();

    // fragment bases: A x4 per m16; B x4 per n8-pair (2 tiles + both K halves)
    uint32_t aH[2], aL[2], bP[4];
    #pragma unroll
    for (int mt = 0; mt < 2; mt++){
        int row = m0 + mt*16 + (lane & 15);
        uint32_t off = row*TSB + ((lane & 16) ? 16 : 0);
        aH[mt] = sb + K1_AH + off;
        aL[mt] = sb + K1_AL + off;
    }
    #pragma unroll
    for (int np = 0; np < 4; np++){
        int row = n0 + np*16 + (lane & 7) + ((lane >> 4) << 3);
        uint32_t off = row*TSB + (((lane >> 3) & 1) << 4);
        bP[np] = sb + K1_BH + off;
    }

    float acc[2][8][4];
    #pragma unroll
    for (int mt = 0; mt < 2; mt++)
        #pragma unroll
        for (int nt = 0; nt < 8; nt++)
            #pragma unroll
            for (int c = 0; c < 4; c++) acc[mt][nt][c] = 0.f;

    #pragma unroll
    for (int ks = 0; ks < 8; ks++){
        const uint32_t kd = ks*32;
        unsigned ah[2][4], al[2][4];
        #pragma unroll
        for (int mt = 0; mt < 2; mt++){
            ldsm4(ah[mt][0], ah[mt][1], ah[mt][2], ah[mt][3], aH[mt] + kd);
            ldsm4(al[mt][0], al[mt][1], al[mt][2], al[mt][3], aL[mt] + kd);
        }
        #pragma unroll
        for (int np = 0; np < 4; np++){
            unsigned b0, b1, b2, b3;
            ldsm4(b0, b1, b2, b3, bP[np] + kd);
            #pragma unroll
            for (int mt = 0; mt < 2; mt++){
                float* a0 = acc[mt][np*2];
                float* a1 = acc[mt][np*2+1];
                mma_f16(a0[0],a0[1],a0[2],a0[3], ah[mt][0],ah[mt][1],ah[mt][2],ah[mt][3], b0,b1);
                mma_f16(a0[0],a0[1],a0[2],a0[3], al[mt][0],al[mt][1],al[mt][2],al[mt][3], b0,b1);
                mma_f16(a1[0],a1[1],a1[2],a1[3], ah[mt][0],ah[mt][1],ah[mt][2],ah[mt][3], b2,b3);
                mma_f16(a1[0],a1[1],a1[2],a1[3], al[mt][0],al[mt][1],al[mt][2],al[mt][3], b2,b3);
            }
        }
    }
    __syncthreads();

    float* red = (float*)smx;           // 256 floats (reuses A region)
    red[tid] = 0.f;
    __syncthreads();

    float wr[2][2][3];
    #pragma unroll
    for (int mt = 0; mt < 2; mt++)
        #pragma unroll
        for (int rh = 0; rh < 2; rh++){
            int r = m0 + mt*16 + g + rh*8;
            wr[mt][rh][0] = __ldg(&w0[r*131+0]);
            wr[mt][rh][1] = __ldg(&w0[r*131+1]);
            wr[mt][rh][2] = __ldg(&w0[r*131+2]);
        }
    float rs[2][2] = {{0,0},{0,0}}, rq[2][2] = {{0,0},{0,0}};
    #pragma unroll
    for (int nt = 0; nt < 8; nt++){
        int c = n0 + nt*8 + tid4*2;
        float r00 = relS[c],     r01 = relS[c+1];
        float r10 = relS[128+c], r11 = relS[129+c];
        float r20 = relS[256+c], r21 = relS[257+c];
        #pragma unroll
        for (int mt = 0; mt < 2; mt++){
            float* a = acc[mt][nt];
            a[0] += wr[mt][0][0]*r00 + wr[mt][0][1]*r10 + wr[mt][0][2]*r20;
            a[1] += wr[mt][0][0]*r01 + wr[mt][0][1]*r11 + wr[mt][0][2]*r21;
            a[2] += wr[mt][1][0]*r00 + wr[mt][1][1]*r10 + wr[mt][1][2]*r20;
            a[3] += wr[mt][1][0]*r01 + wr[mt][1][1]*r11 + wr[mt][1][2]*r21;
            int r0 = m0 + mt*16 + g, r1 = r0 + 8;
            size_t cb = (size_t)(jb + c) * 128;
            d_out0h[cb + r0]       = __float2half_rn(a[0]);
            d_out0h[cb + 128 + r0] = __float2half_rn(a[1]);
            d_out0h[cb + r1]       = __float2half_rn(a[2]);
            d_out0h[cb + 128 + r1] = __float2half_rn(a[3]);
            rs[mt][0] += a[0] + a[1]; rq[mt][0] += a[0]*a[0] + a[1]*a[1];
            rs[mt][1] += a[2] + a[3]; rq[mt][1] += a[2]*a[2] + a[3]*a[3];
        }
    }
    #pragma unroll
    for (int mt = 0; mt < 2; mt++)
        #pragma unroll
        for (int rh = 0; rh < 2; rh++){
            float s = red4sum(rs[mt][rh]);
            float q = red4sum(rq[mt][rh]);
            if (tid4 == 0){
                int r = m0 + mt*16 + g + rh*8;
                atomicAdd(&red[r], s);
                atomicAdd(&red[128 + r], q);
            }
        }
    __syncthreads();
    if (tid < 128){
        atomicAdd(&d_stats[tid],       red[tid]);
        atomicAdd(&d_stats[128 + tid], red[128 + tid]);
    }
}

__global__ void kfm(int which, const float* __restrict__ g, const float* __restrict__ bb){
    int c = threadIdx.x;
    float inv = 1.0f / (float)COLS;
    int so = (which == 0) ? 0 : 256;
    int qo = (which == 0) ? 128 : 512;
    float mean = d_stats[so + c] * inv;
    float var  = d_stats[qo + c] * inv - mean*mean;
    float scl  = g[c] * rsqrtf(var + EPSV);
    if (which == 0){ d_scm0[c] = scl; d_bim0[c] = fmaf(-mean, scl, bb[c]); }
    else           { d_scm1[c] = scl; d_bim1[c] = fmaf(-mean, scl, bb[c]); }
}

// GEMM2: grid (2, 2048): x = row half (adjacent ids share the out0 tile via L2),
// y = j tile. Fused BN+relu on load, stats + max/min pool.
__global__ void __launch_bounds__(256, 2) kg2(){
    extern __shared__ char smx[];
    float* scS = (float*)(smx + K2_SC);     // [0:128) scale, [128:256) bias
    const int tid = threadIdx.x;
    const int lane = tid & 31, wid = tid >> 5;
    const int g = lane >> 2, tid4 = lane & 3;
    const int m0 = (wid & 3) * 32;          // 2 m16 tiles of 128 local rows
    const int wn = wid >> 2;
    const int n0 = wn * 64;                 // 8 n8 tiles (4 pairs)
    const int rowOff = blockIdx.x * 128;
    const int jb = blockIdx.y * 128;
    uint32_t sb = smem_u32(smx);

    if (tid < 128){ scS[tid] = d_scm0[tid]; scS[128 + tid] = d_bim0[tid]; }

    // A fill: pre-split w1 rows [rowOff, rowOff+128)
    for (int e = tid; e < 2048; e += 256){
        int r = e >> 4, kc = e & 15;
        uint32_t d = sb + K2_AH + r*TSB + kc*16;
        cpa16(d, d_w1h + (rowOff + r)*128 + kc*8);
        cpa16(d + (K2_AL - K2_AH), d_w1l + (rowOff + r)*128 + kc*8);
    }
    __syncthreads();                        // scS visible

    // B fill: load out0 col (fp16), BN+relu in fp32, repack fp16, STS.128
    {
        int col = tid >> 1, half = tid & 1;
        const __half* src = d_out0h + (size_t)(jb + col)*128 + half*64;
        char* bh = smx + K2_BH + col*TSB + half*128;
        #pragma unroll
        for (int kc = 0; kc < 8; kc++){
            uint4 v = *(const uint4*)(src + kc*8);
            unsigned w[4] = {v.x, v.y, v.z, v.w};
            unsigned o[4];
            #pragma unroll
            for (int i = 0; i < 4; i++){
                float2 f = __half22float2(*(__half2*)&w[i]);
                int k = half*64 + kc*8 + i*2;
                f.x = fmaxf(fmaf(scS[k],   f.x, scS[128 + k]),   0.f);
                f.y = fmaxf(fmaf(scS[k+1], f.y, scS[128 + k+1]), 0.f);
                __half2 h = __floats2half2_rn(f.x, f.y);
                o[i] = *(unsigned*)&h;
            }
            *(uint4*)(bh + kc*16) = make_uint4(o[0], o[1], o[2], o[3]);
        }
    }
    cpwait();
    __syncthreads();

    uint32_t aH[2], aL[2], bP[4];
    #pragma unroll
    for (int mt = 0; mt < 2; mt++){
        int row = m0 + mt*16 + (lane & 15);
        uint32_t off = row*TSB + ((lane & 16) ? 16 : 0);
        aH[mt] = sb + K2_AH + off;
        aL[mt] = sb + K2_AL + off;
    }
    #pragma unroll
    for (int np = 0; np < 4; np++){
        int row = n0 + np*16 + (lane & 7) + ((lane >> 4) << 3);
        uint32_t off = row*TSB + (((lane >> 3) & 1) << 4);
        bP[np] = sb + K2_BH + off;
    }

    float acc[2][8][4];
    #pragma unroll
    for (int mt = 0; mt < 2; mt++)
        #pragma unroll
        for (int nt = 0; nt < 8; nt++)
            #pragma unroll
            for (int c = 0; c < 4; c++) acc[mt][nt][c] = 0.f;

    #pragma unroll
    for (int ks = 0; ks < 8; ks++){
        const uint32_t kd = ks*32;
        unsigned ah[2][4], al[2][4];
        #pragma unroll
        for (int mt = 0; mt < 2; mt++){
            ldsm4(ah[mt][0], ah[mt][1], ah[mt][2], ah[mt][3], aH[mt] + kd);
            ldsm4(al[mt][0], al[mt][1], al[mt][2], al[mt][3], aL[mt] + kd);
        }
        #pragma unroll
        for (int np = 0; np < 4; np++){
            unsigned b0, b1, b2, b3;
            ldsm4(b0, b1, b2, b3, bP[np] + kd);
            #pragma unroll
            for (int mt = 0; mt < 2; mt++){
                float* a0 = acc[mt][np*2];
                float* a1 = acc[mt][np*2+1];
                mma_f16(a0[0],a0[1],a0[2],a0[3], ah[mt][0],ah[mt][1],ah[mt][2],ah[mt][3], b0,b1);
                mma_f16(a0[0],a0[1],a0[2],a0[3], al[mt][0],al[mt][1],al[mt][2],al[mt][3], b0,b1);
                mma_f16(a1[0],a1[1],a1[2],a1[3], ah[mt][0],ah[mt][1],ah[mt][2],ah[mt][3], b2,b3);
                mma_f16(a1[0],a1[1],a1[2],a1[3], al[mt][0],al[mt][1],al[mt][2],al[mt][3], b2,b3);
            }
        }
    }
    __syncthreads();

    float* red = (float*)smx;               // 256 floats
    red[tid] = 0.f;
    __syncthreads();

    float rs[2][2] = {{0,0},{0,0}}, rq[2][2] = {{0,0},{0,0}};
    float mx[2][2][2], mn[2][2][2];
    #pragma unroll
    for (int mt = 0; mt < 2; mt++)
        #pragma unroll
        for (int rh = 0; rh < 2; rh++)
            #pragma unroll
            for (int qi = 0; qi < 2; qi++){ mx[mt][rh][qi] = -3.4e38f; mn[mt][rh][qi] = 3.4e38f; }

    #pragma unroll
    for (int nt = 0; nt < 8; nt++){
        int qi = nt >> 2;
        #pragma unroll
        for (int mt = 0; mt < 2; mt++){
            float* a = acc[mt][nt];
            rs[mt][0] += a[0] + a[1]; rq[mt][0] += a[0]*a[0] + a[1]*a[1];
            rs[mt][1] += a[2] + a[3]; rq[mt][1] += a[2]*a[2] + a[3]*a[3];
            mx[mt][0][qi] = fmaxf(mx[mt][0][qi], fmaxf(a[0], a[1]));
            mn[mt][0][qi] = fminf(mn[mt][0][qi], fminf(a[0], a[1]));
            mx[mt][1][qi] = fmaxf(mx[mt][1][qi], fmaxf(a[2], a[3]));
            mn[mt][1][qi] = fminf(mn[mt][1][qi], fminf(a[2], a[3]));
        }
    }
    #pragma unroll
    for (int mt = 0; mt < 2; mt++)
        #pragma unroll
        for (int rh = 0; rh < 2; rh++){
            float s = red4sum(rs[mt][rh]);
            float q = red4sum(rq[mt][rh]);
            int rl = m0 + mt*16 + g + rh*8;
            int rg = rowOff + rl;
            #pragma unroll
            for (int qi = 0; qi < 2; qi++){
                float vmx = red4max(mx[mt][rh][qi]);
                float vmn = red4min(mn[mt][rh][qi]);
                if (tid4 == 0){
                    int qg = blockIdx.y*4 + wn*2 + qi;
                    d_pmax[(size_t)qg*256 + rg] = vmx;
                    d_pmin[(size_t)qg*256 + rg] = vmn;
                }
            }
            if (tid4 == 0){
                atomicAdd(&red[rl], s);
                atomicAdd(&red[128 + rl], q);
            }
        }
    __syncthreads();
    if (tid < 128){
        atomicAdd(&d_stats[256 + rowOff + tid], red[tid]);
        atomicAdd(&d_stats[512 + rowOff + tid], red[128 + tid]);
    }
}

// final: out[p][c] = relu(s*pooled + t), pooled = max if s>=0 else min
__global__ void kfin(float* __restrict__ out){
    int c = threadIdx.x;
    int p = blockIdx.x;
    float s = d_scm1[c], t = d_bim1[c];
    float v = (s >= 0.f) ? d_pmax[(size_t)p*256 + c] : d_pmin[(size_t)p*256 + c];
    out[(size_t)p*256 + c] = fmaxf(fmaf(s, v, t), 0.f);
}

// ---------------- launch ----------------
extern "C" void kernel_launch(void* const* d_in, const int* in_sizes, int n_in,
                              void* d_out, int out_size){
    (void)in_sizes; (void)n_in; (void)out_size;
    const float* ffps = (const float*)d_in[0];
    const float* bxyz = (const float*)d_in[1];
    const float* bfeat= (const float*)d_in[2];
    const float* sw0  = (const float*)d_in[3];
    const float* sg0  = (const float*)d_in[4];
    const float* sb0  = (const float*)d_in[5];
    const float* sw1  = (const float*)d_in[6];
    const float* sg1  = (const float*)d_in[7];
    const float* sb1  = (const float*)d_in[8];
    const float* mw0  = (const float*)d_in[9];
    const float* mg0  = (const float*)d_in[10];
    const float* mb0  = (const float*)d_in[11];
    const float* mw1  = (const float*)d_in[12];
    const float* mg1  = (const float*)d_in[13];
    const float* mb1  = (const float*)d_in[14];
    float* out = (float*)d_out;

    cudaFuncSetAttribute(kg1, cudaFuncAttributeMaxDynamicSharedMemorySize, K1_SMEM);
    cudaFuncSetAttribute(kg2, cudaFuncAttributeMaxDynamicSharedMemorySize, K2_SMEM);

    kzero<<<3, 256>>>();
    kwprep<<<(128*128 + 256*128 + 255)/256, 256>>>(mw0, mw1);
    ks1<<<PTOT/256, 256>>>(ffps, sw0);
    kstat<<<64, 256>>>(0, sg0, sb0);
    ks2<<<PTOT*4/256, 256>>>(sw1);
    kstat<<<3, 256>>>(1, sg1, sb1);
    ks3<<<PTOT/256, 256>>>();
    ktr<<<dim3(NPT/32, CF/32, BQ), dim3(32, 8)>>>(bfeat);
    kballq<<<PTOT/8, 256>>>(bxyz);
    kg1<<<COLS/128, 256, K1_SMEM>>>(mw0, bxyz);
    kfm<<<1, 128>>>(0, mg0, mb0);
    kg2<<<dim3(2, COLS/128), 256, K2_SMEM>>>();
    kfm<<<1, 256>>>(1, mg1, mb1);
    kfin<<<PTOT, 256>>>(out);
}

// round 17
// speedup vs baseline: 5.4880x; 1.0046x over previous
#include <cuda_runtime.h>
#include <cuda_fp16.h>
#include <cstdint>

#define BQ   4
#define NPT  16384
#define MQ   2048
#define CF   128
#define NS   32
#define PTOT (BQ*MQ)        // 8192 query points
#define COLS (PTOT*NS)      // 262144 GEMM columns
#define R2   9.0f
#define EPSV 1e-5f

// ---------------- static scratch (allocation-free rule) ----------------
__device__ float d_h0[64*PTOT];
__device__ float d_h1[3*PTOT];
__device__ float d_nxyz[PTOT*3];
__device__ __half d_fh[(size_t)BQ*NPT*CF];          // features fp16 [b][n][c]
__device__ __half d_w0h[128*128];                   // w0 feature part fp16
__device__ __half d_w1h[256*128];                   // w1 fp16
__device__ int   d_idx[COLS];
__device__ __half d_out0h[(size_t)COLS*128];        // pre-BN layer-0 acts, [j][k] fp16
__device__ float d_pmax[(size_t)PTOT*256];          // [q][c]
__device__ float d_pmin[(size_t)PTOT*256];
__device__ float d_stats[768];
__device__ float d_sc0[64], d_bi0[64], d_sc1[3], d_bi1[3];
__device__ float d_scm0[128], d_bim0[128], d_scm1[256], d_bim1[256];

// ---------------- helpers ----------------
__device__ __forceinline__ uint32_t smem_u32(const void* p){
    uint32_t a;
    asm("{ .reg .u64 t; cvta.to.shared.u64 t, %1; cvt.u32.u64 %0, t; }" : "=r"(a) : "l"(p));
    return a;
}
__device__ __forceinline__ void mma_f16(float& c0, float& c1, float& c2, float& c3,
                                        unsigned a0, unsigned a1, unsigned a2, unsigned a3,
                                        unsigned b0, unsigned b1){
    asm volatile("mma.sync.aligned.m16n8k16.row.col.f32.f16.f16.f32 "
        "{%0,%1,%2,%3}, {%4,%5,%6,%7}, {%8,%9}, {%0,%1,%2,%3};"
        : "+f"(c0), "+f"(c1), "+f"(c2), "+f"(c3)
        : "r"(a0), "r"(a1), "r"(a2), "r"(a3), "r"(b0), "r"(b1));
}
__device__ __forceinline__ void ldsm4(unsigned& r0, unsigned& r1, unsigned& r2, unsigned& r3, uint32_t a){
    asm volatile("ldmatrix.sync.aligned.m8n8.x4.shared.b16 {%0,%1,%2,%3}, [%4];"
        : "=r"(r0), "=r"(r1), "=r"(r2), "=r"(r3) : "r"(a));
}
__device__ __forceinline__ void cpa16(uint32_t dst, const void* src){
    asm volatile("cp.async.cg.shared.global [%0], [%1], 16;" :: "r"(dst), "l"(src));
}
__device__ __forceinline__ void cpwait(){
    asm volatile("cp.async.commit_group;\n\tcp.async.wait_group 0;" ::: "memory");
}
__device__ __forceinline__ float red4sum(float v){
    v += __shfl_xor_sync(0xffffffffu, v, 1, 4);
    v += __shfl_xor_sync(0xffffffffu, v, 2, 4);
    return v;
}
__device__ __forceinline__ float red4max(float v){
    v = fmaxf(v, __shfl_xor_sync(0xffffffffu, v, 1, 4));
    v = fmaxf(v, __shfl_xor_sync(0xffffffffu, v, 2, 4));
    return v;
}
__device__ __forceinline__ float red4min(float v){
    v = fminf(v, __shfl_xor_sync(0xffffffffu, v, 1, 4));
    v = fminf(v, __shfl_xor_sync(0xffffffffu, v, 2, 4));
    return v;
}

// ---------------- small kernels ----------------
__global__ void kzero(){
    int i = blockIdx.x*blockDim.x + threadIdx.x;
    if (i < 768) d_stats[i] = 0.f;
}

__global__ void kwprep(const float* __restrict__ w0, const float* __restrict__ w1){
    int i = blockIdx.x*256 + threadIdx.x;
    if (i < 128*128){
        int r = i >> 7, k = i & 127;
        d_w0h[i] = __float2half_rn(w0[r*131 + 3 + k]);
    } else if (i < 128*128 + 256*128){
        int j = i - 128*128;
        d_w1h[j] = __float2half_rn(w1[j]);
    }
}

__global__ void ks1(const float* __restrict__ ffps, const float* __restrict__ w0){
    int p = blockIdx.x*blockDim.x + threadIdx.x;
    float f0 = ffps[p*3+0], f1 = ffps[p*3+1], f2 = ffps[p*3+2];
    #pragma unroll 4
    for (int c = 0; c < 64; c++){
        float v = w0[c*3+0]*f0 + w0[c*3+1]*f1 + w0[c*3+2]*f2;
        d_h0[c*PTOT + p] = v;
    }
}

__global__ void kstat(int which, const float* __restrict__ g, const float* __restrict__ bb){
    __shared__ float ss[256], sq[256];
    int c = blockIdx.x;
    const float* buf = (which == 0 ? d_h0 : d_h1) + c*PTOT;
    float s = 0.f, q = 0.f;
    for (int i = threadIdx.x; i < PTOT; i += 256){
        float v = buf[i]; s += v; q = fmaf(v, v, q);
    }
    ss[threadIdx.x] = s; sq[threadIdx.x] = q; __syncthreads();
    for (int o = 128; o > 0; o >>= 1){
        if (threadIdx.x < o){
            ss[threadIdx.x] += ss[threadIdx.x+o];
            sq[threadIdx.x] += sq[threadIdx.x+o];
        }
        __syncthreads();
    }
    if (threadIdx.x == 0){
        float mean = ss[0] / (float)PTOT;
        float var  = sq[0] / (float)PTOT - mean*mean;
        float scl  = g[c] * rsqrtf(var + EPSV);
        if (which == 0){ d_sc0[c] = scl; d_bi0[c] = fmaf(-mean, scl, bb[c]); }
        else           { d_sc1[c] = scl; d_bi1[c] = fmaf(-mean, scl, bb[c]); }
    }
}

// shift layer 1: 4 threads per point, 16 channels each, shuffle reduce
__global__ void ks2(const float* __restrict__ w1){
    int idx = blockIdx.x*blockDim.x + threadIdx.x;
    int p = idx >> 2, q = idx & 3;
    float a0 = 0.f, a1 = 0.f, a2 = 0.f;
    #pragma unroll 4
    for (int c = q; c < 64; c += 4){
        float v = fmaxf(fmaf(d_sc0[c], d_h0[c*PTOT + p], d_bi0[c]), 0.f);
        a0 = fmaf(w1[c],       v, a0);
        a1 = fmaf(w1[64 + c],  v, a1);
        a2 = fmaf(w1[128 + c], v, a2);
    }
    a0 = red4sum(a0); a1 = red4sum(a1); a2 = red4sum(a2);
    if (q == 0){
        d_h1[p] = a0; d_h1[PTOT + p] = a1; d_h1[2*PTOT + p] = a2;
    }
}

__global__ void ks3(){
    int p = blockIdx.x*blockDim.x + threadIdx.x;
    #pragma unroll
    for (int o = 0; o < 3; o++)
        d_nxyz[p*3 + o] = fmaxf(fmaf(d_sc1[o], d_h1[o*PTOT + p], d_bi1[o]), 0.f);
}

// transpose features (B,C,N) -> [b][n][c] fp16
__global__ void ktr(const float* __restrict__ feat){
    __shared__ float t[32][33];
    int b = blockIdx.z, n0 = blockIdx.x*32, c0 = blockIdx.y*32;
    for (int i = threadIdx.y; i < 32; i += 8)
        t[i][threadIdx.x] = feat[((size_t)b*CF + (c0+i))*NPT + n0 + threadIdx.x];
    __syncthreads();
    for (int i = threadIdx.y; i < 32; i += 8){
        size_t o = ((size_t)b*NPT + (n0+i))*CF + c0 + threadIdx.x;
        d_fh[o] = __float2half_rn(t[threadIdx.x][i]);
    }
}

__global__ void kballq(const float* __restrict__ bxyz){
    int gw = (blockIdx.x*blockDim.x + threadIdx.x) >> 5;
    int lane = threadIdx.x & 31;
    int b = gw >> 11;
    float q0 = d_nxyz[gw*3+0], q1 = d_nxyz[gw*3+1], q2 = d_nxyz[gw*3+2];
    float qq = q0*q0 + q1*q1 + q2*q2;
    const float* xb = bxyz + (size_t)b*NPT*3;
    int cnt = 0, firstIdx = -1;
    for (int base = 0; base < NPT; base += 32){
        int n = base + lane;
        float x0 = xb[n*3+0], x1 = xb[n*3+1], x2 = xb[n*3+2];
        float xx = x0*x0 + x1*x1 + x2*x2;
        float dot = q0*x0 + q1*x1 + q2*x2;
        float d2 = (qq + xx) - 2.0f*dot;
        bool hit = d2 < R2;
        unsigned bal = __ballot_sync(0xffffffffu, hit);
        if (firstIdx < 0 && bal) firstIdx = base + __ffs(bal) - 1;
        if (hit){
            int pos = cnt + __popc(bal & ((1u << lane) - 1u));
            if (pos < NS) d_idx[gw*NS + pos] = n;
        }
        cnt += __popc(bal);
        if (cnt >= NS) break;
    }
    if (cnt < NS){
        int f = (firstIdx < 0) ? 0 : firstIdx;
        if (lane >= cnt) d_idx[gw*NS + lane] = f;
    }
}

// ---------------- GEMM kernels (1-term fp16 HMMA, occ=2, ldsm-x4) ----------------
#define TSB  272
#define K1_AH 0
#define K1_BH 34816
#define K1_REL 69632
#define K1_SMEM (69632 + 1536)
#define K2_AH 0
#define K2_BH 34816
#define K2_SC 69632
#define K2_SMEM (69632 + 1024)

// GEMM1: 128x128 tile of out0 = W0feat @ gathered feats; rel via FFMA epilogue.
__global__ void __launch_bounds__(256, 2) kg1(const float* __restrict__ w0,
                                              const float* __restrict__ bxyz){
    extern __shared__ char smx[];
    float* relS = (float*)(smx + K1_REL);
    const int tid = threadIdx.x;
    const int lane = tid & 31, wid = tid >> 5;
    const int g = lane >> 2, tid4 = lane & 3;
    const int m0 = (wid & 3) * 32;          // 2 m16 tiles
    const int wn = wid >> 2;
    const int n0 = wn * 64;                 // 8 n8 tiles (4 pairs)
    const int jb = blockIdx.x * 128;
    uint32_t sb = smem_u32(smx);

    // A fill: fp16 w0 via cp.async
    for (int e = tid; e < 2048; e += 256){
        int r = e >> 4, kc = e & 15;
        cpa16(sb + K1_AH + r*TSB + kc*16, d_w0h + r*128 + kc*8);
    }
    // B gather (fp16) + rel
    {
        int col = tid >> 1, half = tid & 1;
        int j = jb + col;
        int b = j >> 16;
        int m = (j & 65535) >> 5;
        int n = d_idx[j];
        size_t base = ((size_t)(b*NPT + n))*CF + half*64;
        uint32_t db = sb + K1_BH + col*TSB + half*128;
        #pragma unroll
        for (int i = 0; i < 8; i++)
            cpa16(db + i*16, d_fh + base + i*8);
        if (half == 0){
            const float* xp = bxyz + (size_t)(b*NPT + n)*3;
            const float* qp = d_nxyz + (size_t)(b*MQ + m)*3;
            relS[col]       = xp[0] - qp[0];
            relS[128 + col] = xp[1] - qp[1];
            relS[256 + col] = xp[2] - qp[2];
        }
    }
    cpwait();
    __syncthreads();

    // fragment bases: A x4 per m16; B x4 per n8-pair (2 tiles + both K halves)
    uint32_t aH[2], bP[4];
    #pragma unroll
    for (int mt = 0; mt < 2; mt++){
        int row = m0 + mt*16 + (lane & 15);
        aH[mt] = sb + K1_AH + row*TSB + ((lane & 16) ? 16 : 0);
    }
    #pragma unroll
    for (int np = 0; np < 4; np++){
        int row = n0 + np*16 + (lane & 7) + ((lane >> 4) << 3);
        bP[np] = sb + K1_BH + row*TSB + (((lane >> 3) & 1) << 4);
    }

    float acc[2][8][4];
    #pragma unroll
    for (int mt = 0; mt < 2; mt++)
        #pragma unroll
        for (int nt = 0; nt < 8; nt++)
            #pragma unroll
            for (int c = 0; c < 4; c++) acc[mt][nt][c] = 0.f;

    #pragma unroll
    for (int ks = 0; ks < 8; ks++){
        const uint32_t kd = ks*32;
        unsigned ah[2][4];
        #pragma unroll
        for (int mt = 0; mt < 2; mt++)
            ldsm4(ah[mt][0], ah[mt][1], ah[mt][2], ah[mt][3], aH[mt] + kd);
        #pragma unroll
        for (int np = 0; np < 4; np++){
            unsigned b0, b1, b2, b3;
            ldsm4(b0, b1, b2, b3, bP[np] + kd);
            #pragma unroll
            for (int mt = 0; mt < 2; mt++){
                float* a0 = acc[mt][np*2];
                float* a1 = acc[mt][np*2+1];
                mma_f16(a0[0],a0[1],a0[2],a0[3], ah[mt][0],ah[mt][1],ah[mt][2],ah[mt][3], b0,b1);
                mma_f16(a1[0],a1[1],a1[2],a1[3], ah[mt][0],ah[mt][1],ah[mt][2],ah[mt][3], b2,b3);
            }
        }
    }
    __syncthreads();

    float* red = (float*)smx;           // 256 floats (reuses A region)
    red[tid] = 0.f;
    __syncthreads();

    float wr[2][2][3];
    #pragma unroll
    for (int mt = 0; mt < 2; mt++)
        #pragma unroll
        for (int rh = 0; rh < 2; rh++){
            int r = m0 + mt*16 + g + rh*8;
            wr[mt][rh][0] = __ldg(&w0[r*131+0]);
            wr[mt][rh][1] = __ldg(&w0[r*131+1]);
            wr[mt][rh][2] = __ldg(&w0[r*131+2]);
        }
    float rs[2][2] = {{0,0},{0,0}}, rq[2][2] = {{0,0},{0,0}};
    #pragma unroll
    for (int nt = 0; nt < 8; nt++){
        int c = n0 + nt*8 + tid4*2;
        float r00 = relS[c],     r01 = relS[c+1];
        float r10 = relS[128+c], r11 = relS[129+c];
        float r20 = relS[256+c], r21 = relS[257+c];
        #pragma unroll
        for (int mt = 0; mt < 2; mt++){
            float* a = acc[mt][nt];
            a[0] += wr[mt][0][0]*r00 + wr[mt][0][1]*r10 + wr[mt][0][2]*r20;
            a[1] += wr[mt][0][0]*r01 + wr[mt][0][1]*r11 + wr[mt][0][2]*r21;
            a[2] += wr[mt][1][0]*r00 + wr[mt][1][1]*r10 + wr[mt][1][2]*r20;
            a[3] += wr[mt][1][0]*r01 + wr[mt][1][1]*r11 + wr[mt][1][2]*r21;
            int r0 = m0 + mt*16 + g, r1 = r0 + 8;
            size_t cb = (size_t)(jb + c) * 128;
            d_out0h[cb + r0]       = __float2half_rn(a[0]);
            d_out0h[cb + 128 + r0] = __float2half_rn(a[1]);
            d_out0h[cb + r1]       = __float2half_rn(a[2]);
            d_out0h[cb + 128 + r1] = __float2half_rn(a[3]);
            rs[mt][0] += a[0] + a[1]; rq[mt][0] += a[0]*a[0] + a[1]*a[1];
            rs[mt][1] += a[2] + a[3]; rq[mt][1] += a[2]*a[2] + a[3]*a[3];
        }
    }
    #pragma unroll
    for (int mt = 0; mt < 2; mt++)
        #pragma unroll
        for (int rh = 0; rh < 2; rh++){
            float s = red4sum(rs[mt][rh]);
            float q = red4sum(rq[mt][rh]);
            if (tid4 == 0){
                int r = m0 + mt*16 + g + rh*8;
                atomicAdd(&red[r], s);
                atomicAdd(&red[128 + r], q);
            }
        }
    __syncthreads();
    if (tid < 128){
        atomicAdd(&d_stats[tid],       red[tid]);
        atomicAdd(&d_stats[128 + tid], red[128 + tid]);
    }
}

__global__ void kfm(int which, const float* __restrict__ g, const float* __restrict__ bb){
    int c = threadIdx.x;
    float inv = 1.0f / (float)COLS;
    int so = (which == 0) ? 0 : 256;
    int qo = (which == 0) ? 128 : 512;
    float mean = d_stats[so + c] * inv;
    float var  = d_stats[qo + c] * inv - mean*mean;
    float scl  = g[c] * rsqrtf(var + EPSV);
    if (which == 0){ d_scm0[c] = scl; d_bim0[c] = fmaf(-mean, scl, bb[c]); }
    else           { d_scm1[c] = scl; d_bim1[c] = fmaf(-mean, scl, bb[c]); }
}

// GEMM2: grid (2, 2048): x = row half (adjacent ids share the out0 tile via L2),
// y = j tile. Fused BN+relu on load, stats + max/min pool.
__global__ void __launch_bounds__(256, 2) kg2(){
    extern __shared__ char smx[];
    float* scS = (float*)(smx + K2_SC);     // [0:128) scale, [128:256) bias
    const int tid = threadIdx.x;
    const int lane = tid & 31, wid = tid >> 5;
    const int g = lane >> 2, tid4 = lane & 3;
    const int m0 = (wid & 3) * 32;          // 2 m16 tiles of 128 local rows
    const int wn = wid >> 2;
    const int n0 = wn * 64;                 // 8 n8 tiles (4 pairs)
    const int rowOff = blockIdx.x * 128;
    const int jb = blockIdx.y * 128;
    uint32_t sb = smem_u32(smx);

    if (tid < 128){ scS[tid] = d_scm0[tid]; scS[128 + tid] = d_bim0[tid]; }

    // A fill: fp16 w1 rows [rowOff, rowOff+128)
    for (int e = tid; e < 2048; e += 256){
        int r = e >> 4, kc = e & 15;
        cpa16(sb + K2_AH + r*TSB + kc*16, d_w1h + (rowOff + r)*128 + kc*8);
    }
    __syncthreads();                        // scS visible

    // B fill: load out0 col (fp16), BN+relu in fp32, repack fp16, STS.128
    {
        int col = tid >> 1, half = tid & 1;
        const __half* src = d_out0h + (size_t)(jb + col)*128 + half*64;
        char* bh = smx + K2_BH + col*TSB + half*128;
        #pragma unroll
        for (int kc = 0; kc < 8; kc++){
            uint4 v = *(const uint4*)(src + kc*8);
            unsigned w[4] = {v.x, v.y, v.z, v.w};
            unsigned o[4];
            #pragma unroll
            for (int i = 0; i < 4; i++){
                float2 f = __half22float2(*(__half2*)&w[i]);
                int k = half*64 + kc*8 + i*2;
                f.x = fmaxf(fmaf(scS[k],   f.x, scS[128 + k]),   0.f);
                f.y = fmaxf(fmaf(scS[k+1], f.y, scS[128 + k+1]), 0.f);
                __half2 h = __floats2half2_rn(f.x, f.y);
                o[i] = *(unsigned*)&h;
            }
            *(uint4*)(bh + kc*16) = make_uint4(o[0], o[1], o[2], o[3]);
        }
    }
    cpwait();
    __syncthreads();

    uint32_t aH[2], bP[4];
    #pragma unroll
    for (int mt = 0; mt < 2; mt++){
        int row = m0 + mt*16 + (lane & 15);
        aH[mt] = sb + K2_AH + row*TSB + ((lane & 16) ? 16 : 0);
    }
    #pragma unroll
    for (int np = 0; np < 4; np++){
        int row = n0 + np*16 + (lane & 7) + ((lane >> 4) << 3);
        bP[np] = sb + K2_BH + row*TSB + (((lane >> 3) & 1) << 4);
    }

    float acc[2][8][4];
    #pragma unroll
    for (int mt = 0; mt < 2; mt++)
        #pragma unroll
        for (int nt = 0; nt < 8; nt++)
            #pragma unroll
            for (int c = 0; c < 4; c++) acc[mt][nt][c] = 0.f;

    #pragma unroll
    for (int ks = 0; ks < 8; ks++){
        const uint32_t kd = ks*32;
        unsigned ah[2][4];
        #pragma unroll
        for (int mt = 0; mt < 2; mt++)
            ldsm4(ah[mt][0], ah[mt][1], ah[mt][2], ah[mt][3], aH[mt] + kd);
        #pragma unroll
        for (int np = 0; np < 4; np++){
            unsigned b0, b1, b2, b3;
            ldsm4(b0, b1, b2, b3, bP[np] + kd);
            #pragma unroll
            for (int mt = 0; mt < 2; mt++){
                float* a0 = acc[mt][np*2];
                float* a1 = acc[mt][np*2+1];
                mma_f16(a0[0],a0[1],a0[2],a0[3], ah[mt][0],ah[mt][1],ah[mt][2],ah[mt][3], b0,b1);
                mma_f16(a1[0],a1[1],a1[2],a1[3], ah[mt][0],ah[mt][1],ah[mt][2],ah[mt][3], b2,b3);
            }
        }
    }
    __syncthreads();

    float* red = (float*)smx;               // 256 floats
    red[tid] = 0.f;
    __syncthreads();

    float rs[2][2] = {{0,0},{0,0}}, rq[2][2] = {{0,0},{0,0}};
    float mx[2][2][2], mn[2][2][2];
    #pragma unroll
    for (int mt = 0; mt < 2; mt++)
        #pragma unroll
        for (int rh = 0; rh < 2; rh++)
            #pragma unroll
            for (int qi = 0; qi < 2; qi++){ mx[mt][rh][qi] = -3.4e38f; mn[mt][rh][qi] = 3.4e38f; }

    #pragma unroll
    for (int nt = 0; nt < 8; nt++){
        int qi = nt >> 2;
        #pragma unroll
        for (int mt = 0; mt < 2; mt++){
            float* a = acc[mt][nt];
            rs[mt][0] += a[0] + a[1]; rq[mt][0] += a[0]*a[0] + a[1]*a[1];
            rs[mt][1] += a[2] + a[3]; rq[mt][1] += a[2]*a[2] + a[3]*a[3];
            mx[mt][0][qi] = fmaxf(mx[mt][0][qi], fmaxf(a[0], a[1]));
            mn[mt][0][qi] = fminf(mn[mt][0][qi], fminf(a[0], a[1]));
            mx[mt][1][qi] = fmaxf(mx[mt][1][qi], fmaxf(a[2], a[3]));
            mn[mt][1][qi] = fminf(mn[mt][1][qi], fminf(a[2], a[3]));
        }
    }
    #pragma unroll
    for (int mt = 0; mt < 2; mt++)
        #pragma unroll
        for (int rh = 0; rh < 2; rh++){
            float s = red4sum(rs[mt][rh]);
            float q = red4sum(rq[mt][rh]);
            int rl = m0 + mt*16 + g + rh*8;
            int rg = rowOff + rl;
            #pragma unroll
            for (int qi = 0; qi < 2; qi++){
                float vmx = red4max(mx[mt][rh][qi]);
                float vmn = red4min(mn[mt][rh][qi]);
                if (tid4 == 0){
                    int qg = blockIdx.y*4 + wn*2 + qi;
                    d_pmax[(size_t)qg*256 + rg] = vmx;
                    d_pmin[(size_t)qg*256 + rg] = vmn;
                }
            }
            if (tid4 == 0){
                atomicAdd(&red[rl], s);
                atomicAdd(&red[128 + rl], q);
            }
        }
    __syncthreads();
    if (tid < 128){
        atomicAdd(&d_stats[256 + rowOff + tid], red[tid]);
        atomicAdd(&d_stats[512 + rowOff + tid], red[128 + tid]);
    }
}

// final: out[p][c] = relu(s*pooled + t), pooled = max if s>=0 else min
__global__ void kfin(float* __restrict__ out){
    int c = threadIdx.x;
    int p = blockIdx.x;
    float s = d_scm1[c], t = d_bim1[c];
    float v = (s >= 0.f) ? d_pmax[(size_t)p*256 + c] : d_pmin[(size_t)p*256 + c];
    out[(size_t)p*256 + c] = fmaxf(fmaf(s, v, t), 0.f);
}

// ---------------- launch ----------------
extern "C" void kernel_launch(void* const* d_in, const int* in_sizes, int n_in,
                              void* d_out, int out_size){
    (void)in_sizes; (void)n_in; (void)out_size;
    const float* ffps = (const float*)d_in[0];
    const float* bxyz = (const float*)d_in[1];
    const float* bfeat= (const float*)d_in[2];
    const float* sw0  = (const float*)d_in[3];
    const float* sg0  = (const float*)d_in[4];
    const float* sb0  = (const float*)d_in[5];
    const float* sw1  = (const float*)d_in[6];
    const float* sg1  = (const float*)d_in[7];
    const float* sb1  = (const float*)d_in[8];
    const float* mw0  = (const float*)d_in[9];
    const float* mg0  = (const float*)d_in[10];
    const float* mb0  = (const float*)d_in[11];
    const float* mw1  = (const float*)d_in[12];
    const float* mg1  = (const float*)d_in[13];
    const float* mb1  = (const float*)d_in[14];
    float* out = (float*)d_out;

    cudaFuncSetAttribute(kg1, cudaFuncAttributeMaxDynamicSharedMemorySize, K1_SMEM);
    cudaFuncSetAttribute(kg2, cudaFuncAttributeMaxDynamicSharedMemorySize, K2_SMEM);

    kzero<<<3, 256>>>();
    kwprep<<<(128*128 + 256*128 + 255)/256, 256>>>(mw0, mw1);
    ks1<<<PTOT/256, 256>>>(ffps, sw0);
    kstat<<<64, 256>>>(0, sg0, sb0);
    ks2<<<PTOT*4/256, 256>>>(sw1);
    kstat<<<3, 256>>>(1, sg1, sb1);
    ks3<<<PTOT/256, 256>>>();
    ktr<<<dim3(NPT/32, CF/32, BQ), dim3(32, 8)>>>(bfeat);
    kballq<<<PTOT/8, 256>>>(bxyz);
    kg1<<<COLS/128, 256, K1_SMEM>>>(mw0, bxyz);
    kfm<<<1, 128>>>(0, mg0, mb0);
    kg2<<<dim3(2, COLS/128), 256, K2_SMEM>>>();
    kfm<<<1, 256>>>(1, mg1, mb1);
    kfin<<<PTOT, 256>>>(out);
}